// round 1
// baseline (speedup 1.0000x reference)
#include <cuda_runtime.h>

#define NP 100      // proxies
#define NS 1024     // samples
#define NN 1124     // total nodes
#define D  512

// scratch (device globals; no allocation allowed)
__device__ float g_A[NN * D];    // layer input / final features
__device__ float g_HW[NN * D];   // h = in @ W
__device__ float g_B[NN * D];    // layer output
__device__ float g_lsrc[NN];
__device__ float g_ldst[NN];

__device__ __forceinline__ float lrelu(float v) { return v > 0.f ? v : 0.2f * v; }

// ---------------------------------------------------------------- concat
__global__ void k_concat(const float* __restrict__ x, const float* __restrict__ prox) {
    int i = blockIdx.x * blockDim.x + threadIdx.x;   // float4 index
    const int pd4 = NP * D / 4;     // 12800
    const int tot4 = NN * D / 4;    // 143872
    if (i >= tot4) return;
    float4 v;
    if (i < pd4) v = reinterpret_cast<const float4*>(prox)[i];
    else         v = reinterpret_cast<const float4*>(x)[i - pd4];
    reinterpret_cast<float4*>(g_A)[i] = v;
}

// ---------------------------------------------------------------- GEMM
// C[M,N] = A[M,K] @ B[K,N] (+bias). 64x64 tile, BK=16, 256 threads, 4x4/thread.
#define BM 64
#define BN 64
#define BK 16
__global__ void k_gemm(const float* __restrict__ A, const float* __restrict__ B,
                       float* __restrict__ C, int M, int N, int K,
                       const float* __restrict__ bias) {
    __shared__ float As[BK][BM];
    __shared__ float Bs[BK][BN];
    int tid = threadIdx.x;
    int tx = tid & 15, ty = tid >> 4;
    int m0 = blockIdx.y * BM, n0 = blockIdx.x * BN;

    int la = tid * 4;
    int ar = la >> 4, ac = la & 15;     // A tile coords (64 rows x 16 cols)
    int br = la >> 6, bc = la & 63;     // B tile coords (16 rows x 64 cols)

    float acc[4][4] = {};

    for (int k0 = 0; k0 < K; k0 += BK) {
        float4 av = make_float4(0.f, 0.f, 0.f, 0.f);
        if (m0 + ar < M)
            av = *reinterpret_cast<const float4*>(A + (size_t)(m0 + ar) * K + k0 + ac);
        As[ac + 0][ar] = av.x; As[ac + 1][ar] = av.y;
        As[ac + 2][ar] = av.z; As[ac + 3][ar] = av.w;

        float4 bv = make_float4(0.f, 0.f, 0.f, 0.f);
        {
            const float* brow = B + (size_t)(k0 + br) * N;
            int gc = n0 + bc;
            if (gc + 3 < N) bv = *reinterpret_cast<const float4*>(brow + gc);
            else {
                if (gc + 0 < N) bv.x = brow[gc + 0];
                if (gc + 1 < N) bv.y = brow[gc + 1];
                if (gc + 2 < N) bv.z = brow[gc + 2];
            }
        }
        *reinterpret_cast<float4*>(&Bs[br][bc]) = bv;
        __syncthreads();

        #pragma unroll
        for (int kk = 0; kk < BK; kk++) {
            float a0 = As[kk][ty * 4 + 0], a1 = As[kk][ty * 4 + 1];
            float a2 = As[kk][ty * 4 + 2], a3 = As[kk][ty * 4 + 3];
            float b0 = Bs[kk][tx * 4 + 0], b1 = Bs[kk][tx * 4 + 1];
            float b2 = Bs[kk][tx * 4 + 2], b3 = Bs[kk][tx * 4 + 3];
            acc[0][0] += a0 * b0; acc[0][1] += a0 * b1; acc[0][2] += a0 * b2; acc[0][3] += a0 * b3;
            acc[1][0] += a1 * b0; acc[1][1] += a1 * b1; acc[1][2] += a1 * b2; acc[1][3] += a1 * b3;
            acc[2][0] += a2 * b0; acc[2][1] += a2 * b1; acc[2][2] += a2 * b2; acc[2][3] += a2 * b3;
            acc[3][0] += a3 * b0; acc[3][1] += a3 * b1; acc[3][2] += a3 * b2; acc[3][3] += a3 * b3;
        }
        __syncthreads();
    }

    #pragma unroll
    for (int i = 0; i < 4; i++) {
        int r = m0 + ty * 4 + i;
        if (r >= M) continue;
        #pragma unroll
        for (int j = 0; j < 4; j++) {
            int c = n0 + tx * 4 + j;
            if (c >= N) continue;
            float v = acc[i][j];
            if (bias) v += bias[c];
            C[(size_t)r * N + c] = v;
        }
    }
}

// ---------------------------------------------------------------- logits
// l_src[i] = H[i]·a_src ; l_dst[i] = H[i]·a_dst  (one warp per row)
__global__ void k_logits(const float* __restrict__ H, const float* __restrict__ a_src,
                         const float* __restrict__ a_dst) {
    int warp = (blockIdx.x * blockDim.x + threadIdx.x) >> 5;
    int lane = threadIdx.x & 31;
    if (warp >= NN) return;
    const float* h = H + (size_t)warp * D;
    float s = 0.f, t = 0.f;
    #pragma unroll 4
    for (int d = lane; d < D; d += 32) {
        float v = h[d];
        s += v * a_src[d];
        t += v * a_dst[d];
    }
    #pragma unroll
    for (int o = 16; o > 0; o >>= 1) {
        s += __shfl_xor_sync(0xffffffffu, s, o);
        t += __shfl_xor_sync(0xffffffffu, t, o);
    }
    if (lane == 0) { g_lsrc[warp] = s; g_ldst[warp] = t; }
}

// ---------------------------------------------------------------- attention: sample destinations
// one block (128 thr) per sample; softmax over 100 proxies + self, then weighted sum.
__global__ void k_attn_samples(const float* __restrict__ HW,
                               const float* __restrict__ bias,
                               float* __restrict__ out) {
    __shared__ float w[NP];
    __shared__ float sh[4];
    __shared__ float s_m, s_invz, s_wself;
    int s = blockIdx.x;
    int node = NP + s;
    int tid = threadIdx.x;

    float ld = g_ldst[node];
    float ev = -1e30f;
    if (tid < NP) ev = lrelu(g_lsrc[tid] + ld);
    float eself = lrelu(g_lsrc[node] + ld);

    // block max
    float m = ev;
    #pragma unroll
    for (int o = 16; o > 0; o >>= 1) m = fmaxf(m, __shfl_xor_sync(0xffffffffu, m, o));
    if ((tid & 31) == 0) sh[tid >> 5] = m;
    __syncthreads();
    if (tid == 0)
        s_m = fmaxf(fmaxf(fmaxf(sh[0], sh[1]), fmaxf(sh[2], sh[3])), eself);
    __syncthreads();
    m = s_m;

    float wv = 0.f;
    if (tid < NP) { wv = expf(ev - m); w[tid] = wv; }
    float ps = wv;
    #pragma unroll
    for (int o = 16; o > 0; o >>= 1) ps += __shfl_xor_sync(0xffffffffu, ps, o);
    if ((tid & 31) == 0) sh[tid >> 5] = ps;
    __syncthreads();
    if (tid == 0) {
        float wself = expf(eself - m);
        s_wself = wself;
        s_invz = 1.f / (sh[0] + sh[1] + sh[2] + sh[3] + wself);
    }
    __syncthreads();
    float invz = s_invz, wself = s_wself;

    for (int d = tid; d < D; d += 128) {
        float acc = wself * HW[(size_t)node * D + d];
        #pragma unroll 4
        for (int p = 0; p < NP; p++) acc += w[p] * HW[(size_t)p * D + d];
        float o = acc * invz + bias[d];
        out[(size_t)node * D + d] = o > 0.f ? o : 0.f;
    }
}

// ---------------------------------------------------------------- attention: proxy destinations
// grid (100, 4): block = (proxy p, 128-wide d chunk). softmax over 1024 samples + self.
__global__ void k_attn_proxies(const float* __restrict__ HW,
                               const float* __restrict__ bias,
                               float* __restrict__ out) {
    __shared__ float w[NS];
    __shared__ float sh[4];
    __shared__ float s_m, s_invz;
    int p = blockIdx.x;
    int tid = threadIdx.x;

    float ld = g_ldst[p];
    float ev[8];
    float m = -1e30f;
    #pragma unroll
    for (int i = 0; i < 8; i++) {
        int s = tid + i * 128;
        float v = lrelu(g_lsrc[NP + s] + ld);
        ev[i] = v;
        m = fmaxf(m, v);
    }
    float eself = lrelu(g_lsrc[p] + ld);

    #pragma unroll
    for (int o = 16; o > 0; o >>= 1) m = fmaxf(m, __shfl_xor_sync(0xffffffffu, m, o));
    if ((tid & 31) == 0) sh[tid >> 5] = m;
    __syncthreads();
    if (tid == 0)
        s_m = fmaxf(fmaxf(fmaxf(sh[0], sh[1]), fmaxf(sh[2], sh[3])), eself);
    __syncthreads();
    m = s_m;

    float ps = 0.f;
    #pragma unroll
    for (int i = 0; i < 8; i++) {
        float wv = expf(ev[i] - m);
        w[tid + i * 128] = wv;
        ps += wv;
    }
    #pragma unroll
    for (int o = 16; o > 0; o >>= 1) ps += __shfl_xor_sync(0xffffffffu, ps, o);
    if ((tid & 31) == 0) sh[tid >> 5] = ps;
    __syncthreads();
    if (tid == 0)
        s_invz = 1.f / (sh[0] + sh[1] + sh[2] + sh[3] + expf(eself - m));
    __syncthreads();
    float invz = s_invz;
    float wself = expf(eself - m);

    int d = blockIdx.y * 128 + tid;
    float acc = wself * HW[(size_t)p * D + d];
    #pragma unroll 8
    for (int s = 0; s < NS; s++) acc += w[s] * HW[(size_t)(NP + s) * D + d];
    float o = acc * invz + bias[d];
    out[(size_t)p * D + d] = o > 0.f ? o : 0.f;
}

// ---------------------------------------------------------------- output h copy
__global__ void k_copy_out(const float* __restrict__ src, float* __restrict__ dst, int n4) {
    int i = blockIdx.x * blockDim.x + threadIdx.x;
    if (i < n4)
        reinterpret_cast<float4*>(dst)[i] = reinterpret_cast<const float4*>(src)[i];
}

// ---------------------------------------------------------------- launch
extern "C" void kernel_launch(void* const* d_in, const int* in_sizes, int n_in,
                              void* d_out, int out_size) {
    const float* x    = (const float*)d_in[0];
    const float* prox = (const float*)d_in[1];
    const float* W1   = (const float*)d_in[2];
    const float* as1  = (const float*)d_in[3];
    const float* ad1  = (const float*)d_in[4];
    const float* b1   = (const float*)d_in[5];
    const float* W2   = (const float*)d_in[6];
    const float* as2  = (const float*)d_in[7];
    const float* ad2  = (const float*)d_in[8];
    const float* b2   = (const float*)d_in[9];
    const float* fcw  = (const float*)d_in[10];
    const float* fcb  = (const float*)d_in[11];
    float* out = (float*)d_out;

    float *pA, *pHW, *pB;
    cudaGetSymbolAddress((void**)&pA,  g_A);
    cudaGetSymbolAddress((void**)&pHW, g_HW);
    cudaGetSymbolAddress((void**)&pB,  g_B);

    // concat [proxies; x] -> g_A
    k_concat<<<(NN * D / 4 + 255) / 256, 256>>>(x, prox);

    dim3 gemm_grid(D / BN, (NN + BM - 1) / BM);   // (8, 18)

    // ---- layer 1: g_A -> g_HW -> g_B
    k_gemm<<<gemm_grid, 256>>>(pA, W1, pHW, NN, D, D, nullptr);
    k_logits<<<(NN * 32 + 255) / 256, 256>>>(pHW, as1, ad1);
    k_attn_samples<<<NS, 128>>>(pHW, b1, pB);
    k_attn_proxies<<<dim3(NP, 4), 128>>>(pHW, b1, pB);

    // ---- layer 2: g_B -> g_HW -> g_A
    k_gemm<<<gemm_grid, 256>>>(pB, W2, pHW, NN, D, D, nullptr);
    k_logits<<<(NN * 32 + 255) / 256, 256>>>(pHW, as2, ad2);
    k_attn_samples<<<NS, 128>>>(pHW, b2, pA);
    k_attn_proxies<<<dim3(NP, 4), 128>>>(pHW, b2, pA);

    // ---- outputs: preds = g_A[NP:] @ fcw + fcb ; h = g_A[NP:]
    dim3 fc_grid((100 + BN - 1) / BN, NS / BM);   // (2, 16)
    k_gemm<<<fc_grid, 256>>>(pA + NP * D, fcw, out, NS, 100, D, fcb);
    k_copy_out<<<(NS * D / 4 + 255) / 256, 256>>>(pA + NP * D, out + NS * 100, NS * D / 4);
}

// round 2
// speedup vs baseline: 1.7115x; 1.7115x over previous
#include <cuda_runtime.h>

#define NP 100      // proxies
#define NS 1024     // samples
#define NN 1124     // total nodes
#define D  512
#define KPAD 112    // NP padded to multiple of 16
#define SPLITK 8    // split-K parts for proxy aggregation

// scratch (device globals; no allocation allowed)
__device__ float g_A[NN * D];
__device__ float g_HW[NN * D];
__device__ float g_B[NN * D];
__device__ float g_lsrc[NN];
__device__ float g_ldst[NN];
__device__ float g_alphaS[NS * KPAD];   // normalized alpha, sample destinations
__device__ float g_aselfS[NS];
__device__ float g_alphaP[NP * NS];     // normalized alpha, proxy destinations
__device__ float g_aselfP[NP];
__device__ float g_ppart[SPLITK * NP * D];

__device__ __forceinline__ float lrelu(float v) { return v > 0.f ? v : 0.2f * v; }

// ---------------------------------------------------------------- concat
__global__ void k_concat(const float* __restrict__ x, const float* __restrict__ prox) {
    int i = blockIdx.x * blockDim.x + threadIdx.x;
    const int pd4 = NP * D / 4;
    const int tot4 = NN * D / 4;
    if (i >= tot4) return;
    float4 v;
    if (i < pd4) v = reinterpret_cast<const float4*>(prox)[i];
    else         v = reinterpret_cast<const float4*>(x)[i - pd4];
    reinterpret_cast<float4*>(g_A)[i] = v;
}

// ---------------------------------------------------------------- GEMM (general, for X@W and FC)
#define BM 64
#define BN 64
#define BK 16
__global__ void k_gemm(const float* __restrict__ A, const float* __restrict__ B,
                       float* __restrict__ C, int M, int N, int K,
                       const float* __restrict__ bias) {
    __shared__ float As[BK][BM];
    __shared__ float Bs[BK][BN];
    int tid = threadIdx.x;
    int tx = tid & 15, ty = tid >> 4;
    int m0 = blockIdx.y * BM, n0 = blockIdx.x * BN;

    int la = tid * 4;
    int ar = la >> 4, ac = la & 15;
    int br = la >> 6, bc = la & 63;

    float acc[4][4] = {};

    for (int k0 = 0; k0 < K; k0 += BK) {
        float4 av = make_float4(0.f, 0.f, 0.f, 0.f);
        if (m0 + ar < M)
            av = *reinterpret_cast<const float4*>(A + (size_t)(m0 + ar) * K + k0 + ac);
        As[ac + 0][ar] = av.x; As[ac + 1][ar] = av.y;
        As[ac + 2][ar] = av.z; As[ac + 3][ar] = av.w;

        float4 bv = make_float4(0.f, 0.f, 0.f, 0.f);
        {
            const float* brow = B + (size_t)(k0 + br) * N;
            int gc = n0 + bc;
            if (gc + 3 < N) bv = *reinterpret_cast<const float4*>(brow + gc);
            else {
                if (gc + 0 < N) bv.x = brow[gc + 0];
                if (gc + 1 < N) bv.y = brow[gc + 1];
                if (gc + 2 < N) bv.z = brow[gc + 2];
            }
        }
        *reinterpret_cast<float4*>(&Bs[br][bc]) = bv;
        __syncthreads();

        #pragma unroll
        for (int kk = 0; kk < BK; kk++) {
            float a0 = As[kk][ty * 4 + 0], a1 = As[kk][ty * 4 + 1];
            float a2 = As[kk][ty * 4 + 2], a3 = As[kk][ty * 4 + 3];
            float b0 = Bs[kk][tx * 4 + 0], b1 = Bs[kk][tx * 4 + 1];
            float b2 = Bs[kk][tx * 4 + 2], b3 = Bs[kk][tx * 4 + 3];
            acc[0][0] += a0 * b0; acc[0][1] += a0 * b1; acc[0][2] += a0 * b2; acc[0][3] += a0 * b3;
            acc[1][0] += a1 * b0; acc[1][1] += a1 * b1; acc[1][2] += a1 * b2; acc[1][3] += a1 * b3;
            acc[2][0] += a2 * b0; acc[2][1] += a2 * b1; acc[2][2] += a2 * b2; acc[2][3] += a2 * b3;
            acc[3][0] += a3 * b0; acc[3][1] += a3 * b1; acc[3][2] += a3 * b2; acc[3][3] += a3 * b3;
        }
        __syncthreads();
    }

    #pragma unroll
    for (int i = 0; i < 4; i++) {
        int r = m0 + ty * 4 + i;
        if (r >= M) continue;
        #pragma unroll
        for (int j = 0; j < 4; j++) {
            int c = n0 + tx * 4 + j;
            if (c >= N) continue;
            float v = acc[i][j];
            if (bias) v += bias[c];
            C[(size_t)r * N + c] = v;
        }
    }
}

// ---------------------------------------------------------------- logits
__global__ void k_logits(const float* __restrict__ H, const float* __restrict__ a_src,
                         const float* __restrict__ a_dst) {
    int warp = (blockIdx.x * blockDim.x + threadIdx.x) >> 5;
    int lane = threadIdx.x & 31;
    if (warp >= NN) return;
    const float* h = H + (size_t)warp * D;
    float s = 0.f, t = 0.f;
    #pragma unroll 4
    for (int d = lane; d < D; d += 32) {
        float v = h[d];
        s += v * a_src[d];
        t += v * a_dst[d];
    }
    #pragma unroll
    for (int o = 16; o > 0; o >>= 1) {
        s += __shfl_xor_sync(0xffffffffu, s, o);
        t += __shfl_xor_sync(0xffffffffu, t, o);
    }
    if (lane == 0) { g_lsrc[warp] = s; g_ldst[warp] = t; }
}

// ---------------------------------------------------------------- alpha (sample destinations)
// one warp per sample: softmax over 100 proxies + self -> normalized alphaS + aselfS
__global__ void k_alpha_samples() {
    int warp = (blockIdx.x * blockDim.x + threadIdx.x) >> 5;
    int lane = threadIdx.x & 31;
    if (warp >= NS) return;
    int node = NP + warp;
    float ld = g_ldst[node];
    float e[4];
    #pragma unroll
    for (int i = 0; i < 4; i++) {
        int p = lane + 32 * i;
        e[i] = (p < NP) ? lrelu(g_lsrc[p] + ld) : -1e30f;
    }
    float eself = lrelu(g_lsrc[node] + ld);

    float m = fmaxf(fmaxf(e[0], e[1]), fmaxf(e[2], e[3]));
    #pragma unroll
    for (int o = 16; o > 0; o >>= 1) m = fmaxf(m, __shfl_xor_sync(0xffffffffu, m, o));
    m = fmaxf(m, eself);

    float w[4], sum = 0.f;
    #pragma unroll
    for (int i = 0; i < 4; i++) {
        int p = lane + 32 * i;
        w[i] = (p < NP) ? expf(e[i] - m) : 0.f;
        sum += w[i];
    }
    #pragma unroll
    for (int o = 16; o > 0; o >>= 1) sum += __shfl_xor_sync(0xffffffffu, sum, o);
    float wself = expf(eself - m);
    float inv = 1.f / (sum + wself);

    #pragma unroll
    for (int i = 0; i < 4; i++) {
        int p = lane + 32 * i;
        if (p < KPAD) g_alphaS[(size_t)warp * KPAD + p] = w[i] * inv;
    }
    if (lane == 0) g_aselfS[warp] = wself * inv;
}

// ---------------------------------------------------------------- alpha (proxy destinations)
// one block (256 thr) per proxy: softmax over 1024 samples + self
__global__ void k_alpha_proxies() {
    __shared__ float sh[8];
    __shared__ float s_m, s_inv;
    int p = blockIdx.x;
    int tid = threadIdx.x;
    float ld = g_ldst[p];

    float e[4];
    float m = -1e30f;
    #pragma unroll
    for (int i = 0; i < 4; i++) {
        int s = tid + i * 256;
        e[i] = lrelu(g_lsrc[NP + s] + ld);
        m = fmaxf(m, e[i]);
    }
    float eself = lrelu(g_lsrc[p] + ld);

    #pragma unroll
    for (int o = 16; o > 0; o >>= 1) m = fmaxf(m, __shfl_xor_sync(0xffffffffu, m, o));
    if ((tid & 31) == 0) sh[tid >> 5] = m;
    __syncthreads();
    if (tid == 0) {
        float mm = sh[0];
        #pragma unroll
        for (int i = 1; i < 8; i++) mm = fmaxf(mm, sh[i]);
        s_m = fmaxf(mm, eself);
    }
    __syncthreads();
    m = s_m;

    float w[4], sum = 0.f;
    #pragma unroll
    for (int i = 0; i < 4; i++) { w[i] = expf(e[i] - m); sum += w[i]; }
    #pragma unroll
    for (int o = 16; o > 0; o >>= 1) sum += __shfl_xor_sync(0xffffffffu, sum, o);
    if ((tid & 31) == 0) sh[tid >> 5] = sum;
    __syncthreads();
    if (tid == 0) {
        float ss = 0.f;
        #pragma unroll
        for (int i = 0; i < 8; i++) ss += sh[i];
        s_inv = 1.f / (ss + expf(eself - m));
    }
    __syncthreads();
    float inv = s_inv;

    #pragma unroll
    for (int i = 0; i < 4; i++)
        g_alphaP[(size_t)p * NS + tid + i * 256] = w[i] * inv;
    if (tid == 0) g_aselfP[p] = expf(eself - m) * inv;
}

// ---------------------------------------------------------------- sample aggregation GEMM
// out[NP+r] = relu( alphaS[r,:] @ HW[0:KPAD] + aselfS[r]*HW[NP+r] + bias )
__global__ void k_agg_samples(const float* __restrict__ HW,
                              const float* __restrict__ bias,
                              float* __restrict__ out) {
    __shared__ float As[BK][BM];
    __shared__ float Bs[BK][BN];
    int tid = threadIdx.x;
    int tx = tid & 15, ty = tid >> 4;
    int m0 = blockIdx.y * BM, n0 = blockIdx.x * BN;

    int la = tid * 4;
    int ar = la >> 4, ac = la & 15;
    int br = la >> 6, bc = la & 63;

    float acc[4][4] = {};

    #pragma unroll
    for (int k0 = 0; k0 < KPAD; k0 += BK) {
        float4 av = *reinterpret_cast<const float4*>(g_alphaS + (size_t)(m0 + ar) * KPAD + k0 + ac);
        As[ac + 0][ar] = av.x; As[ac + 1][ar] = av.y;
        As[ac + 2][ar] = av.z; As[ac + 3][ar] = av.w;

        float4 bv = *reinterpret_cast<const float4*>(HW + (size_t)(k0 + br) * D + n0 + bc);
        *reinterpret_cast<float4*>(&Bs[br][bc]) = bv;
        __syncthreads();

        #pragma unroll
        for (int kk = 0; kk < BK; kk++) {
            float a0 = As[kk][ty * 4 + 0], a1 = As[kk][ty * 4 + 1];
            float a2 = As[kk][ty * 4 + 2], a3 = As[kk][ty * 4 + 3];
            float b0 = Bs[kk][tx * 4 + 0], b1 = Bs[kk][tx * 4 + 1];
            float b2 = Bs[kk][tx * 4 + 2], b3 = Bs[kk][tx * 4 + 3];
            acc[0][0] += a0 * b0; acc[0][1] += a0 * b1; acc[0][2] += a0 * b2; acc[0][3] += a0 * b3;
            acc[1][0] += a1 * b0; acc[1][1] += a1 * b1; acc[1][2] += a1 * b2; acc[1][3] += a1 * b3;
            acc[2][0] += a2 * b0; acc[2][1] += a2 * b1; acc[2][2] += a2 * b2; acc[2][3] += a2 * b3;
            acc[3][0] += a3 * b0; acc[3][1] += a3 * b1; acc[3][2] += a3 * b2; acc[3][3] += a3 * b3;
        }
        __syncthreads();
    }

    #pragma unroll
    for (int i = 0; i < 4; i++) {
        int r = m0 + ty * 4 + i;          // sample index 0..1023
        float aself = g_aselfS[r];
        #pragma unroll
        for (int j = 0; j < 4; j++) {
            int c = n0 + tx * 4 + j;
            float v = acc[i][j] + aself * HW[(size_t)(NP + r) * D + c] + bias[c];
            out[(size_t)(NP + r) * D + c] = v > 0.f ? v : 0.f;
        }
    }
}

// ---------------------------------------------------------------- proxy aggregation GEMM (split-K)
// partial[z][p,c] = alphaP[p, z*128:(z+1)*128] @ HW[NP+z*128 : NP+(z+1)*128]
__global__ void k_agg_prox_part(const float* __restrict__ HW) {
    __shared__ float As[BK][BM];
    __shared__ float Bs[BK][BN];
    int tid = threadIdx.x;
    int tx = tid & 15, ty = tid >> 4;
    int m0 = blockIdx.y * BM, n0 = blockIdx.x * BN;
    int kbase = blockIdx.z * (NS / SPLITK);   // 128 per part

    int la = tid * 4;
    int ar = la >> 4, ac = la & 15;
    int br = la >> 6, bc = la & 63;

    float acc[4][4] = {};

    #pragma unroll
    for (int kk0 = 0; kk0 < NS / SPLITK; kk0 += BK) {
        int k0 = kbase + kk0;
        float4 av = make_float4(0.f, 0.f, 0.f, 0.f);
        if (m0 + ar < NP)
            av = *reinterpret_cast<const float4*>(g_alphaP + (size_t)(m0 + ar) * NS + k0 + ac);
        As[ac + 0][ar] = av.x; As[ac + 1][ar] = av.y;
        As[ac + 2][ar] = av.z; As[ac + 3][ar] = av.w;

        float4 bv = *reinterpret_cast<const float4*>(HW + (size_t)(NP + k0 + br) * D + n0 + bc);
        *reinterpret_cast<float4*>(&Bs[br][bc]) = bv;
        __syncthreads();

        #pragma unroll
        for (int kk = 0; kk < BK; kk++) {
            float a0 = As[kk][ty * 4 + 0], a1 = As[kk][ty * 4 + 1];
            float a2 = As[kk][ty * 4 + 2], a3 = As[kk][ty * 4 + 3];
            float b0 = Bs[kk][tx * 4 + 0], b1 = Bs[kk][tx * 4 + 1];
            float b2 = Bs[kk][tx * 4 + 2], b3 = Bs[kk][tx * 4 + 3];
            acc[0][0] += a0 * b0; acc[0][1] += a0 * b1; acc[0][2] += a0 * b2; acc[0][3] += a0 * b3;
            acc[1][0] += a1 * b0; acc[1][1] += a1 * b1; acc[1][2] += a1 * b2; acc[1][3] += a1 * b3;
            acc[2][0] += a2 * b0; acc[2][1] += a2 * b1; acc[2][2] += a2 * b2; acc[2][3] += a2 * b3;
            acc[3][0] += a3 * b0; acc[3][1] += a3 * b1; acc[3][2] += a3 * b2; acc[3][3] += a3 * b3;
        }
        __syncthreads();
    }

    float* part = g_ppart + (size_t)blockIdx.z * NP * D;
    #pragma unroll
    for (int i = 0; i < 4; i++) {
        int r = m0 + ty * 4 + i;
        if (r >= NP) continue;
        #pragma unroll
        for (int j = 0; j < 4; j++) {
            int c = n0 + tx * 4 + j;
            part[(size_t)r * D + c] = acc[i][j];
        }
    }
}

// finalize proxies: sum parts + self + bias, relu
__global__ void k_prox_fin(const float* __restrict__ HW,
                           const float* __restrict__ bias,
                           float* __restrict__ out) {
    int idx = blockIdx.x * blockDim.x + threadIdx.x;
    if (idx >= NP * D) return;
    int p = idx / D, c = idx - p * D;
    float v = 0.f;
    #pragma unroll
    for (int z = 0; z < SPLITK; z++) v += g_ppart[(size_t)z * NP * D + idx];
    v += g_aselfP[p] * HW[(size_t)p * D + c] + bias[c];
    out[(size_t)p * D + c] = v > 0.f ? v : 0.f;
}

// ---------------------------------------------------------------- output h copy
__global__ void k_copy_out(const float* __restrict__ src, float* __restrict__ dst, int n4) {
    int i = blockIdx.x * blockDim.x + threadIdx.x;
    if (i < n4)
        reinterpret_cast<float4*>(dst)[i] = reinterpret_cast<const float4*>(src)[i];
}

// ---------------------------------------------------------------- launch
extern "C" void kernel_launch(void* const* d_in, const int* in_sizes, int n_in,
                              void* d_out, int out_size) {
    const float* x    = (const float*)d_in[0];
    const float* prox = (const float*)d_in[1];
    const float* W1   = (const float*)d_in[2];
    const float* as1  = (const float*)d_in[3];
    const float* ad1  = (const float*)d_in[4];
    const float* b1   = (const float*)d_in[5];
    const float* W2   = (const float*)d_in[6];
    const float* as2  = (const float*)d_in[7];
    const float* ad2  = (const float*)d_in[8];
    const float* b2   = (const float*)d_in[9];
    const float* fcw  = (const float*)d_in[10];
    const float* fcb  = (const float*)d_in[11];
    float* out = (float*)d_out;

    float *pA, *pHW, *pB;
    cudaGetSymbolAddress((void**)&pA,  g_A);
    cudaGetSymbolAddress((void**)&pHW, g_HW);
    cudaGetSymbolAddress((void**)&pB,  g_B);

    k_concat<<<(NN * D / 4 + 255) / 256, 256>>>(x, prox);

    dim3 gemm_grid(D / BN, (NN + BM - 1) / BM);         // (8, 18)
    dim3 aggs_grid(D / BN, NS / BM);                    // (8, 16)
    dim3 aggp_grid(D / BN, (NP + BM - 1) / BM, SPLITK); // (8, 2, 8)

    // ---- layer 1: g_A -> g_HW -> g_B
    k_gemm<<<gemm_grid, 256>>>(pA, W1, pHW, NN, D, D, nullptr);
    k_logits<<<(NN * 32 + 255) / 256, 256>>>(pHW, as1, ad1);
    k_alpha_samples<<<NS / 8, 256>>>();
    k_alpha_proxies<<<NP, 256>>>();
    k_agg_samples<<<aggs_grid, 256>>>(pHW, b1, pB);
    k_agg_prox_part<<<aggp_grid, 256>>>(pHW);
    k_prox_fin<<<(NP * D + 255) / 256, 256>>>(pHW, b1, pB);

    // ---- layer 2: g_B -> g_HW -> g_A
    k_gemm<<<gemm_grid, 256>>>(pB, W2, pHW, NN, D, D, nullptr);
    k_logits<<<(NN * 32 + 255) / 256, 256>>>(pHW, as2, ad2);
    k_alpha_samples<<<NS / 8, 256>>>();
    k_alpha_proxies<<<NP, 256>>>();
    k_agg_samples<<<aggs_grid, 256>>>(pHW, b2, pA);
    k_agg_prox_part<<<aggp_grid, 256>>>(pHW);
    k_prox_fin<<<(NP * D + 255) / 256, 256>>>(pHW, b2, pA);

    // ---- outputs
    dim3 fc_grid((100 + BN - 1) / BN, NS / BM);   // (2, 16)
    k_gemm<<<fc_grid, 256>>>(pA + NP * D, fcw, out, NS, 100, D, fcb);
    k_copy_out<<<(NS * D / 4 + 255) / 256, 256>>>(pA + NP * D, out + NS * 100, NS * D / 4);
}

// round 4
// speedup vs baseline: 2.1489x; 1.2555x over previous
#include <cuda_runtime.h>
#include <cuda_bf16.h>
#include <cstdint>

#define NP 100      // proxies
#define NS 1024     // samples
#define NN 1124     // total nodes
#define MPAD 1152   // NN padded to 128
#define D  512
#define KPAD 112    // NP padded to multiple of 16
#define SPLITK 8    // split-K parts for proxy aggregation

// scratch (device globals; no allocation allowed)
__device__ float g_A[NN * D];
__device__ float g_HW[NN * D];
__device__ float g_B[NN * D];
__device__ float g_lsrc[NN];
__device__ float g_ldst[NN];
__device__ float g_alphaS[NS * KPAD];
__device__ float g_aselfS[NS];
__device__ float g_alphaP[NP * NS];
__device__ float g_aselfP[NP];
__device__ float g_ppart[SPLITK * NP * D];
// bf16 split operands for tensor-core GEMM
__device__ __nv_bfloat16 g_Ah[MPAD * D];
__device__ __nv_bfloat16 g_Al[MPAD * D];
__device__ __nv_bfloat16 g_Wh[D * D];   // transposed: [N, K] K-major
__device__ __nv_bfloat16 g_Wl[D * D];

__device__ __forceinline__ float lrelu(float v) { return v > 0.f ? v : 0.2f * v; }

__device__ __forceinline__ uint32_t smem_u32(const void* p) {
    uint32_t a;
    asm("{ .reg .u64 t; cvta.to.shared.u64 t, %1; cvt.u32.u64 %0, t; }" : "=r"(a) : "l"(p));
    return a;
}

// ============================ conversion kernels ============================
// pack 4 consecutive values into hi/lo bf16x2 pairs
__device__ __forceinline__ void split_store4(int base, float4 v) {
    __nv_bfloat16 h0 = __float2bfloat16(v.x), h1 = __float2bfloat16(v.y);
    __nv_bfloat16 h2 = __float2bfloat16(v.z), h3 = __float2bfloat16(v.w);
    __nv_bfloat16 l0 = __float2bfloat16(v.x - __bfloat162float(h0));
    __nv_bfloat16 l1 = __float2bfloat16(v.y - __bfloat162float(h1));
    __nv_bfloat16 l2 = __float2bfloat16(v.z - __bfloat162float(h2));
    __nv_bfloat16 l3 = __float2bfloat16(v.w - __bfloat162float(h3));
    *reinterpret_cast<__nv_bfloat162*>(g_Ah + base)     = __nv_bfloat162(h0, h1);
    *reinterpret_cast<__nv_bfloat162*>(g_Ah + base + 2) = __nv_bfloat162(h2, h3);
    *reinterpret_cast<__nv_bfloat162*>(g_Al + base)     = __nv_bfloat162(l0, l1);
    *reinterpret_cast<__nv_bfloat162*>(g_Al + base + 2) = __nv_bfloat162(l2, l3);
}

// layer-1 input: concat [proxies; x], pad rows to MPAD with zeros
__global__ void k_cvt_in(const float* __restrict__ x, const float* __restrict__ prox) {
    int i4 = blockIdx.x * blockDim.x + threadIdx.x;
    if (i4 >= MPAD * D / 4) return;
    int base = i4 * 4;
    int row = base >> 9;
    float4 v = make_float4(0.f, 0.f, 0.f, 0.f);
    if (row < NP)       v = *reinterpret_cast<const float4*>(prox + base);
    else if (row < NN)  v = *reinterpret_cast<const float4*>(x + base - NP * D);
    split_store4(base, v);
}

// layer-2 input: from fp32 activations (NN rows), pad to MPAD
__global__ void k_cvt_act(const float* __restrict__ src) {
    int i4 = blockIdx.x * blockDim.x + threadIdx.x;
    if (i4 >= MPAD * D / 4) return;
    int base = i4 * 4;
    int row = base >> 9;
    float4 v = make_float4(0.f, 0.f, 0.f, 0.f);
    if (row < NN) v = *reinterpret_cast<const float4*>(src + base);
    split_store4(base, v);
}

// W [K,N] -> transposed split [N,K] bf16 hi/lo
__global__ void k_cvt_w(const float* __restrict__ W) {
    __shared__ float t[32][33];
    int tx = threadIdx.x & 31, ty = threadIdx.x >> 5;   // 32 x 8
    int k0 = blockIdx.y * 32, n0 = blockIdx.x * 32;
    #pragma unroll
    for (int j = 0; j < 4; j++)
        t[ty + 8 * j][tx] = W[(size_t)(k0 + ty + 8 * j) * D + n0 + tx];
    __syncthreads();
    #pragma unroll
    for (int j = 0; j < 4; j++) {
        int n = n0 + ty + 8 * j, k = k0 + tx;
        float v = t[tx][ty + 8 * j];
        __nv_bfloat16 hi = __float2bfloat16(v);
        g_Wh[(size_t)n * D + k] = hi;
        g_Wl[(size_t)n * D + k] = __float2bfloat16(v - __bfloat162float(hi));
    }
}

// ============================ tensor-core GEMM: g_HW = A @ W ============================
// block 64x64, 8 warps (2m x 4n), warp tile 32x16, BK=64, 3-pass bf16 split.
// smem tiles: Ah | Al | Bh | Bl, each 64 rows x 128 bytes, xor-swizzled.
#define SWB(r, b) ((r) * 128 + ((b) ^ (((r) & 7) << 4)))

__device__ __forceinline__ void ldm_x4(uint32_t* f, uint32_t addr) {
    asm volatile("ldmatrix.sync.aligned.m8n8.x4.shared.b16 {%0,%1,%2,%3}, [%4];"
                 : "=r"(f[0]), "=r"(f[1]), "=r"(f[2]), "=r"(f[3]) : "r"(addr));
}
__device__ __forceinline__ void ldm_x2(uint32_t* f, uint32_t addr) {
    asm volatile("ldmatrix.sync.aligned.m8n8.x2.shared.b16 {%0,%1}, [%2];"
                 : "=r"(f[0]), "=r"(f[1]) : "r"(addr));
}
__device__ __forceinline__ void mma_bf16(float* c, const uint32_t* a, const uint32_t* b) {
    asm volatile(
        "mma.sync.aligned.m16n8k16.row.col.f32.bf16.bf16.f32 "
        "{%0,%1,%2,%3}, {%4,%5,%6,%7}, {%8,%9}, {%0,%1,%2,%3};"
        : "+f"(c[0]), "+f"(c[1]), "+f"(c[2]), "+f"(c[3])
        : "r"(a[0]), "r"(a[1]), "r"(a[2]), "r"(a[3]), "r"(b[0]), "r"(b[1]));
}

__global__ void __launch_bounds__(256, 1) k_mma_gemm() {
    __shared__ __align__(16) char sm[32768];   // Ah 8K | Al 8K | Bh 8K | Bl 8K
    int tid = threadIdx.x, wid = tid >> 5, lane = tid & 31;
    int n0 = blockIdx.x * 64, m0 = blockIdx.y * 64;
    int wm = (wid >> 2) * 32, wn = (wid & 3) * 16;

    uint32_t sb = smem_u32(sm);

    // ldmatrix lane addressing (within-tile byte offsets)
    int a_r = (lane & 7) + ((lane >> 3) & 1) * 8;     // row within 16-row A tile
    int a_kb = (lane >> 4) * 16;                      // kbyte 0 / 16
    int b_r = lane & 7;                               // row within 8-row B tile
    int b_kb = ((lane >> 3) & 1) * 16;

    float acc[2][2][4] = {};

    for (int c = 0; c < D / 64; c++) {
        int kc = c * 64;
        // ---- load 4 operand tiles (each 64x64 bf16 = 8KB)
        #pragma unroll
        for (int o = 0; o < 4; o++) {
            const __nv_bfloat16* src;
            int rbase;
            if (o == 0)      { src = g_Ah; rbase = m0; }
            else if (o == 1) { src = g_Al; rbase = m0; }
            else if (o == 2) { src = g_Wh; rbase = n0; }
            else             { src = g_Wl; rbase = n0; }
            char* dst = sm + o * 8192;
            #pragma unroll
            for (int q = 0; q < 2; q++) {
                int i = tid * 2 + q;            // 0..511 16B-slots
                int r = i >> 3, s = i & 7;
                uint4 v = *reinterpret_cast<const uint4*>(src + (size_t)(rbase + r) * D + kc + s * 8);
                *reinterpret_cast<uint4*>(dst + SWB(r, s * 16)) = v;
            }
        }
        __syncthreads();

        #pragma unroll
        for (int ks = 0; ks < 4; ks++) {
            int kb = ks * 32;
            uint32_t ah[2][4], al[2][4], bh[2][2], bl[2][2];
            #pragma unroll
            for (int mt = 0; mt < 2; mt++) {
                int r = wm + mt * 16 + a_r;
                ldm_x4(ah[mt], sb + 0    + SWB(r, kb + a_kb));
                ldm_x4(al[mt], sb + 8192 + SWB(r, kb + a_kb));
            }
            #pragma unroll
            for (int nt = 0; nt < 2; nt++) {
                int r = wn + nt * 8 + b_r;
                ldm_x2(bh[nt], sb + 16384 + SWB(r, kb + b_kb));
                ldm_x2(bl[nt], sb + 24576 + SWB(r, kb + b_kb));
            }
            #pragma unroll
            for (int mt = 0; mt < 2; mt++)
                #pragma unroll
                for (int nt = 0; nt < 2; nt++) {
                    mma_bf16(acc[mt][nt], ah[mt], bh[nt]);
                    mma_bf16(acc[mt][nt], ah[mt], bl[nt]);
                    mma_bf16(acc[mt][nt], al[mt], bh[nt]);
                }
        }
        __syncthreads();
    }

    // epilogue
    #pragma unroll
    for (int mt = 0; mt < 2; mt++) {
        int row = m0 + wm + mt * 16 + (lane >> 2);
        #pragma unroll
        for (int nt = 0; nt < 2; nt++) {
            int col = n0 + wn + nt * 8 + (lane & 3) * 2;
            if (row < NN)
                *reinterpret_cast<float2*>(g_HW + (size_t)row * D + col) =
                    make_float2(acc[mt][nt][0], acc[mt][nt][1]);
            if (row + 8 < NN)
                *reinterpret_cast<float2*>(g_HW + (size_t)(row + 8) * D + col) =
                    make_float2(acc[mt][nt][2], acc[mt][nt][3]);
        }
    }
}

// ============================ fp32 GEMM (FC head) ============================
#define BM 64
#define BN 64
#define BK 16
__global__ void k_gemm(const float* __restrict__ A, const float* __restrict__ B,
                       float* __restrict__ C, int M, int N, int K,
                       const float* __restrict__ bias) {
    __shared__ float As[BK][BM];
    __shared__ float Bs[BK][BN];
    int tid = threadIdx.x;
    int tx = tid & 15, ty = tid >> 4;
    int m0 = blockIdx.y * BM, n0 = blockIdx.x * BN;

    int la = tid * 4;
    int ar = la >> 4, ac = la & 15;
    int br = la >> 6, bc = la & 63;

    float acc[4][4] = {};

    for (int k0 = 0; k0 < K; k0 += BK) {
        float4 av = make_float4(0.f, 0.f, 0.f, 0.f);
        if (m0 + ar < M)
            av = *reinterpret_cast<const float4*>(A + (size_t)(m0 + ar) * K + k0 + ac);
        As[ac + 0][ar] = av.x; As[ac + 1][ar] = av.y;
        As[ac + 2][ar] = av.z; As[ac + 3][ar] = av.w;

        float4 bv = make_float4(0.f, 0.f, 0.f, 0.f);
        {
            const float* brow = B + (size_t)(k0 + br) * N;
            int gc = n0 + bc;
            if (gc + 3 < N) bv = *reinterpret_cast<const float4*>(brow + gc);
            else {
                if (gc + 0 < N) bv.x = brow[gc + 0];
                if (gc + 1 < N) bv.y = brow[gc + 1];
                if (gc + 2 < N) bv.z = brow[gc + 2];
            }
        }
        *reinterpret_cast<float4*>(&Bs[br][bc]) = bv;
        __syncthreads();

        #pragma unroll
        for (int kk = 0; kk < BK; kk++) {
            float a0 = As[kk][ty * 4 + 0], a1 = As[kk][ty * 4 + 1];
            float a2 = As[kk][ty * 4 + 2], a3 = As[kk][ty * 4 + 3];
            float b0 = Bs[kk][tx * 4 + 0], b1 = Bs[kk][tx * 4 + 1];
            float b2 = Bs[kk][tx * 4 + 2], b3 = Bs[kk][tx * 4 + 3];
            acc[0][0] += a0 * b0; acc[0][1] += a0 * b1; acc[0][2] += a0 * b2; acc[0][3] += a0 * b3;
            acc[1][0] += a1 * b0; acc[1][1] += a1 * b1; acc[1][2] += a1 * b2; acc[1][3] += a1 * b3;
            acc[2][0] += a2 * b0; acc[2][1] += a2 * b1; acc[2][2] += a2 * b2; acc[2][3] += a2 * b3;
            acc[3][0] += a3 * b0; acc[3][1] += a3 * b1; acc[3][2] += a3 * b2; acc[3][3] += a3 * b3;
        }
        __syncthreads();
    }

    #pragma unroll
    for (int i = 0; i < 4; i++) {
        int r = m0 + ty * 4 + i;
        if (r >= M) continue;
        #pragma unroll
        for (int j = 0; j < 4; j++) {
            int c = n0 + tx * 4 + j;
            if (c >= N) continue;
            float v = acc[i][j];
            if (bias) v += bias[c];
            C[(size_t)r * N + c] = v;
        }
    }
}

// ============================ logits ============================
__global__ void k_logits(const float* __restrict__ H, const float* __restrict__ a_src,
                         const float* __restrict__ a_dst) {
    int warp = (blockIdx.x * blockDim.x + threadIdx.x) >> 5;
    int lane = threadIdx.x & 31;
    if (warp >= NN) return;
    const float* h = H + (size_t)warp * D;
    float s = 0.f, t = 0.f;
    #pragma unroll 4
    for (int d = lane; d < D; d += 32) {
        float v = h[d];
        s += v * a_src[d];
        t += v * a_dst[d];
    }
    #pragma unroll
    for (int o = 16; o > 0; o >>= 1) {
        s += __shfl_xor_sync(0xffffffffu, s, o);
        t += __shfl_xor_sync(0xffffffffu, t, o);
    }
    if (lane == 0) { g_lsrc[warp] = s; g_ldst[warp] = t; }
}

// ============================ alpha kernels ============================
__global__ void k_alpha_samples() {
    int warp = (blockIdx.x * blockDim.x + threadIdx.x) >> 5;
    int lane = threadIdx.x & 31;
    if (warp >= NS) return;
    int node = NP + warp;
    float ld = g_ldst[node];
    float e[4];
    #pragma unroll
    for (int i = 0; i < 4; i++) {
        int p = lane + 32 * i;
        e[i] = (p < NP) ? lrelu(g_lsrc[p] + ld) : -1e30f;
    }
    float eself = lrelu(g_lsrc[node] + ld);

    float m = fmaxf(fmaxf(e[0], e[1]), fmaxf(e[2], e[3]));
    #pragma unroll
    for (int o = 16; o > 0; o >>= 1) m = fmaxf(m, __shfl_xor_sync(0xffffffffu, m, o));
    m = fmaxf(m, eself);

    float w[4], sum = 0.f;
    #pragma unroll
    for (int i = 0; i < 4; i++) {
        int p = lane + 32 * i;
        w[i] = (p < NP) ? expf(e[i] - m) : 0.f;
        sum += w[i];
    }
    #pragma unroll
    for (int o = 16; o > 0; o >>= 1) sum += __shfl_xor_sync(0xffffffffu, sum, o);
    float wself = expf(eself - m);
    float inv = 1.f / (sum + wself);

    #pragma unroll
    for (int i = 0; i < 4; i++) {
        int p = lane + 32 * i;
        if (p < KPAD) g_alphaS[(size_t)warp * KPAD + p] = w[i] * inv;
    }
    if (lane == 0) g_aselfS[warp] = wself * inv;
}

__global__ void k_alpha_proxies() {
    __shared__ float sh[8];
    __shared__ float s_m, s_inv;
    int p = blockIdx.x;
    int tid = threadIdx.x;
    float ld = g_ldst[p];

    float e[4];
    float m = -1e30f;
    #pragma unroll
    for (int i = 0; i < 4; i++) {
        int s = tid + i * 256;
        e[i] = lrelu(g_lsrc[NP + s] + ld);
        m = fmaxf(m, e[i]);
    }
    float eself = lrelu(g_lsrc[p] + ld);

    #pragma unroll
    for (int o = 16; o > 0; o >>= 1) m = fmaxf(m, __shfl_xor_sync(0xffffffffu, m, o));
    if ((tid & 31) == 0) sh[tid >> 5] = m;
    __syncthreads();
    if (tid == 0) {
        float mm = sh[0];
        #pragma unroll
        for (int i = 1; i < 8; i++) mm = fmaxf(mm, sh[i]);
        s_m = fmaxf(mm, eself);
    }
    __syncthreads();
    m = s_m;

    float w[4], sum = 0.f;
    #pragma unroll
    for (int i = 0; i < 4; i++) { w[i] = expf(e[i] - m); sum += w[i]; }
    #pragma unroll
    for (int o = 16; o > 0; o >>= 1) sum += __shfl_xor_sync(0xffffffffu, sum, o);
    if ((tid & 31) == 0) sh[tid >> 5] = sum;
    __syncthreads();
    if (tid == 0) {
        float ss = 0.f;
        #pragma unroll
        for (int i = 0; i < 8; i++) ss += sh[i];
        s_inv = 1.f / (ss + expf(eself - m));
    }
    __syncthreads();
    float inv = s_inv;

    #pragma unroll
    for (int i = 0; i < 4; i++)
        g_alphaP[(size_t)p * NS + tid + i * 256] = w[i] * inv;
    if (tid == 0) g_aselfP[p] = expf(eself - m) * inv;
}

// ============================ aggregation GEMMs ============================
__global__ void k_agg_samples(const float* __restrict__ HW,
                              const float* __restrict__ bias,
                              float* __restrict__ out) {
    __shared__ float As[BK][BM];
    __shared__ float Bs[BK][BN];
    int tid = threadIdx.x;
    int tx = tid & 15, ty = tid >> 4;
    int m0 = blockIdx.y * BM, n0 = blockIdx.x * BN;

    int la = tid * 4;
    int ar = la >> 4, ac = la & 15;
    int br = la >> 6, bc = la & 63;

    float acc[4][4] = {};

    #pragma unroll
    for (int k0 = 0; k0 < KPAD; k0 += BK) {
        float4 av = *reinterpret_cast<const float4*>(g_alphaS + (size_t)(m0 + ar) * KPAD + k0 + ac);
        As[ac + 0][ar] = av.x; As[ac + 1][ar] = av.y;
        As[ac + 2][ar] = av.z; As[ac + 3][ar] = av.w;

        float4 bv = *reinterpret_cast<const float4*>(HW + (size_t)(k0 + br) * D + n0 + bc);
        *reinterpret_cast<float4*>(&Bs[br][bc]) = bv;
        __syncthreads();

        #pragma unroll
        for (int kk = 0; kk < BK; kk++) {
            float a0 = As[kk][ty * 4 + 0], a1 = As[kk][ty * 4 + 1];
            float a2 = As[kk][ty * 4 + 2], a3 = As[kk][ty * 4 + 3];
            float b0 = Bs[kk][tx * 4 + 0], b1 = Bs[kk][tx * 4 + 1];
            float b2 = Bs[kk][tx * 4 + 2], b3 = Bs[kk][tx * 4 + 3];
            acc[0][0] += a0 * b0; acc[0][1] += a0 * b1; acc[0][2] += a0 * b2; acc[0][3] += a0 * b3;
            acc[1][0] += a1 * b0; acc[1][1] += a1 * b1; acc[1][2] += a1 * b2; acc[1][3] += a1 * b3;
            acc[2][0] += a2 * b0; acc[2][1] += a2 * b1; acc[2][2] += a2 * b2; acc[2][3] += a2 * b3;
            acc[3][0] += a3 * b0; acc[3][1] += a3 * b1; acc[3][2] += a3 * b2; acc[3][3] += a3 * b3;
        }
        __syncthreads();
    }

    #pragma unroll
    for (int i = 0; i < 4; i++) {
        int r = m0 + ty * 4 + i;
        float aself = g_aselfS[r];
        #pragma unroll
        for (int j = 0; j < 4; j++) {
            int c = n0 + tx * 4 + j;
            float v = acc[i][j] + aself * HW[(size_t)(NP + r) * D + c] + bias[c];
            out[(size_t)(NP + r) * D + c] = v > 0.f ? v : 0.f;
        }
    }
}

__global__ void k_agg_prox_part(const float* __restrict__ HW) {
    __shared__ float As[BK][BM];
    __shared__ float Bs[BK][BN];
    int tid = threadIdx.x;
    int tx = tid & 15, ty = tid >> 4;
    int m0 = blockIdx.y * BM, n0 = blockIdx.x * BN;
    int kbase = blockIdx.z * (NS / SPLITK);

    int la = tid * 4;
    int ar = la >> 4, ac = la & 15;
    int br = la >> 6, bc = la & 63;

    float acc[4][4] = {};

    #pragma unroll
    for (int kk0 = 0; kk0 < NS / SPLITK; kk0 += BK) {
        int k0 = kbase + kk0;
        float4 av = make_float4(0.f, 0.f, 0.f, 0.f);
        if (m0 + ar < NP)
            av = *reinterpret_cast<const float4*>(g_alphaP + (size_t)(m0 + ar) * NS + k0 + ac);
        As[ac + 0][ar] = av.x; As[ac + 1][ar] = av.y;
        As[ac + 2][ar] = av.z; As[ac + 3][ar] = av.w;

        float4 bv = *reinterpret_cast<const float4*>(HW + (size_t)(NP + k0 + br) * D + n0 + bc);
        *reinterpret_cast<float4*>(&Bs[br][bc]) = bv;
        __syncthreads();

        #pragma unroll
        for (int kk = 0; kk < BK; kk++) {
            float a0 = As[kk][ty * 4 + 0], a1 = As[kk][ty * 4 + 1];
            float a2 = As[kk][ty * 4 + 2], a3 = As[kk][ty * 4 + 3];
            float b0 = Bs[kk][tx * 4 + 0], b1 = Bs[kk][tx * 4 + 1];
            float b2 = Bs[kk][tx * 4 + 2], b3 = Bs[kk][tx * 4 + 3];
            acc[0][0] += a0 * b0; acc[0][1] += a0 * b1; acc[0][2] += a0 * b2; acc[0][3] += a0 * b3;
            acc[1][0] += a1 * b0; acc[1][1] += a1 * b1; acc[1][2] += a1 * b2; acc[1][3] += a1 * b3;
            acc[2][0] += a2 * b0; acc[2][1] += a2 * b1; acc[2][2] += a2 * b2; acc[2][3] += a2 * b3;
            acc[3][0] += a3 * b0; acc[3][1] += a3 * b1; acc[3][2] += a3 * b2; acc[3][3] += a3 * b3;
        }
        __syncthreads();
    }

    float* part = g_ppart + (size_t)blockIdx.z * NP * D;
    #pragma unroll
    for (int i = 0; i < 4; i++) {
        int r = m0 + ty * 4 + i;
        if (r >= NP) continue;
        #pragma unroll
        for (int j = 0; j < 4; j++) {
            int c = n0 + tx * 4 + j;
            part[(size_t)r * D + c] = acc[i][j];
        }
    }
}

__global__ void k_prox_fin(const float* __restrict__ HW,
                           const float* __restrict__ bias,
                           float* __restrict__ out) {
    int idx = blockIdx.x * blockDim.x + threadIdx.x;
    if (idx >= NP * D) return;
    int p = idx / D, c = idx - p * D;
    float v = 0.f;
    #pragma unroll
    for (int z = 0; z < SPLITK; z++) v += g_ppart[(size_t)z * NP * D + idx];
    v += g_aselfP[p] * HW[(size_t)p * D + c] + bias[c];
    out[(size_t)p * D + c] = v > 0.f ? v : 0.f;
}

// ============================ output h copy ============================
__global__ void k_copy_out(const float* __restrict__ src, float* __restrict__ dst, int n4) {
    int i = blockIdx.x * blockDim.x + threadIdx.x;
    if (i < n4)
        reinterpret_cast<float4*>(dst)[i] = reinterpret_cast<const float4*>(src)[i];
}

// ============================ launch ============================
extern "C" void kernel_launch(void* const* d_in, const int* in_sizes, int n_in,
                              void* d_out, int out_size) {
    const float* x    = (const float*)d_in[0];
    const float* prox = (const float*)d_in[1];
    const float* W1   = (const float*)d_in[2];
    const float* as1  = (const float*)d_in[3];
    const float* ad1  = (const float*)d_in[4];
    const float* b1   = (const float*)d_in[5];
    const float* W2   = (const float*)d_in[6];
    const float* as2  = (const float*)d_in[7];
    const float* ad2  = (const float*)d_in[8];
    const float* b2   = (const float*)d_in[9];
    const float* fcw  = (const float*)d_in[10];
    const float* fcb  = (const float*)d_in[11];
    float* out = (float*)d_out;

    float *pA, *pHW, *pB;
    cudaGetSymbolAddress((void**)&pA,  g_A);
    cudaGetSymbolAddress((void**)&pHW, g_HW);
    cudaGetSymbolAddress((void**)&pB,  g_B);

    dim3 mma_grid(D / 64, MPAD / 64);                   // (8, 18)
    dim3 cvtw_grid(D / 32, D / 32);                     // (16, 16)
    dim3 aggs_grid(D / BN, NS / BM);                    // (8, 16)
    dim3 aggp_grid(D / BN, (NP + BM - 1) / BM, SPLITK); // (8, 2, 8)
    int cvt_blocks = (MPAD * D / 4 + 255) / 256;

    // ---- layer 1
    k_cvt_in<<<cvt_blocks, 256>>>(x, prox);
    k_cvt_w<<<cvtw_grid, 256>>>(W1);
    k_mma_gemm<<<mma_grid, 256>>>();
    k_logits<<<(NN * 32 + 255) / 256, 256>>>(pHW, as1, ad1);
    k_alpha_samples<<<NS / 8, 256>>>();
    k_alpha_proxies<<<NP, 256>>>();
    k_agg_samples<<<aggs_grid, 256>>>(pHW, b1, pB);
    k_agg_prox_part<<<aggp_grid, 256>>>(pHW);
    k_prox_fin<<<(NP * D + 255) / 256, 256>>>(pHW, b1, pB);

    // ---- layer 2
    k_cvt_act<<<cvt_blocks, 256>>>(pB);
    k_cvt_w<<<cvtw_grid, 256>>>(W2);
    k_mma_gemm<<<mma_grid, 256>>>();
    k_logits<<<(NN * 32 + 255) / 256, 256>>>(pHW, as2, ad2);
    k_alpha_samples<<<NS / 8, 256>>>();
    k_alpha_proxies<<<NP, 256>>>();
    k_agg_samples<<<aggs_grid, 256>>>(pHW, b2, pA);
    k_agg_prox_part<<<aggp_grid, 256>>>(pHW);
    k_prox_fin<<<(NP * D + 255) / 256, 256>>>(pHW, b2, pA);

    // ---- outputs
    dim3 fc_grid((100 + BN - 1) / BN, NS / BM);   // (2, 16)
    k_gemm<<<fc_grid, 256>>>(pA + NP * D, fcw, out, NS, 100, D, fcb);
    k_copy_out<<<(NS * D / 4 + 255) / 256, 256>>>(pA + NP * D, out + NS * 100, NS * D / 4);
}

// round 5
// speedup vs baseline: 2.7018x; 1.2573x over previous
#include <cuda_runtime.h>
#include <cuda_bf16.h>
#include <cstdint>

#define NP 100      // proxies
#define NS 1024     // samples
#define NN 1124     // total nodes
#define MPAD 1152   // NN padded to 128
#define D  512
#define KPAD 112    // NP padded to multiple of 16
#define SPLITK 8    // split-K parts for proxy aggregation

// scratch (device globals; no allocation allowed)
__device__ float g_A[NN * D];
__device__ float g_HW[NN * D];
__device__ float g_B[NN * D];
__device__ float g_lsrc[NN];
__device__ float g_ldst[NN];
__device__ float g_alphaS[NS * KPAD];
__device__ float g_aselfS[NS];
__device__ float g_alphaP[NP * NS];
__device__ float g_aselfP[NP];
__device__ float g_ppart[SPLITK * NP * D];
__device__ float g_v[4][D];             // W1@as1, W1@ad1, W2@as2, W2@ad2
// bf16 split operands for tensor-core GEMM
__device__ __nv_bfloat16 g_Ah[MPAD * D];
__device__ __nv_bfloat16 g_Al[MPAD * D];
__device__ __nv_bfloat16 g_W1h[D * D];  // transposed [N,K]
__device__ __nv_bfloat16 g_W1l[D * D];
__device__ __nv_bfloat16 g_W2h[D * D];
__device__ __nv_bfloat16 g_W2l[D * D];

__device__ __forceinline__ float lrelu(float v) { return v > 0.f ? v : 0.2f * v; }

__device__ __forceinline__ uint32_t smem_u32(const void* p) {
    uint32_t a;
    asm("{ .reg .u64 t; cvta.to.shared.u64 t, %1; cvt.u32.u64 %0, t; }" : "=r"(a) : "l"(p));
    return a;
}

// ============================ prep: W transpose/split + W@a matvecs ============================
// grid (16,16,3): z=0 -> W1 transpose, z=1 -> W2 transpose, z=2 -> 4 matvecs
__global__ void k_prep(const float* __restrict__ W1, const float* __restrict__ W2,
                       const float* __restrict__ as1, const float* __restrict__ ad1,
                       const float* __restrict__ as2, const float* __restrict__ ad2) {
    if (blockIdx.z < 2) {
        const float* W = blockIdx.z ? W2 : W1;
        __nv_bfloat16* Wh = blockIdx.z ? g_W2h : g_W1h;
        __nv_bfloat16* Wl = blockIdx.z ? g_W2l : g_W1l;
        __shared__ float t[32][33];
        int tx = threadIdx.x & 31, ty = threadIdx.x >> 5;
        int k0 = blockIdx.y * 32, n0 = blockIdx.x * 32;
        #pragma unroll
        for (int j = 0; j < 4; j++)
            t[ty + 8 * j][tx] = W[(size_t)(k0 + ty + 8 * j) * D + n0 + tx];
        __syncthreads();
        #pragma unroll
        for (int j = 0; j < 4; j++) {
            int n = n0 + ty + 8 * j, k = k0 + tx;
            float v = t[tx][ty + 8 * j];
            __nv_bfloat16 hi = __float2bfloat16(v);
            Wh[(size_t)n * D + k] = hi;
            Wl[(size_t)n * D + k] = __float2bfloat16(v - __bfloat162float(hi));
        }
    } else {
        // matvecs: 2048 warps total; this z-slice has 256 blocks * 8 warps
        int b = blockIdx.y * 16 + blockIdx.x;
        int gw = b * 8 + (threadIdx.x >> 5);
        int lane = threadIdx.x & 31;
        int vec = gw >> 9, k = gw & 511;
        const float* W = (vec < 2) ? W1 : W2;
        const float* a = (vec == 0) ? as1 : (vec == 1) ? ad1 : (vec == 2) ? as2 : ad2;
        const float* wr = W + (size_t)k * D;
        float s = 0.f;
        #pragma unroll 4
        for (int n = lane; n < D; n += 32) s += wr[n] * a[n];
        #pragma unroll
        for (int o = 16; o > 0; o >>= 1) s += __shfl_xor_sync(0xffffffffu, s, o);
        if (lane == 0) g_v[vec][k] = s;
    }
}

// ============================ convert + logits ============================
// one block per row (128 thr): bf16 hi/lo split of the row + dot with v_s, v_d.
// layer1: src = concat(prox, x); layer2: src = g_B.
__global__ void k_cvt_log(const float* __restrict__ x, const float* __restrict__ prox,
                          const float* __restrict__ act, int vbase) {
    __shared__ float sh[8];
    int row = blockIdx.x, tid = threadIdx.x;
    int base = row * D + tid * 4;

    float4 v = make_float4(0.f, 0.f, 0.f, 0.f);
    if (act) {
        if (row < NN) v = *reinterpret_cast<const float4*>(act + base);
    } else {
        if (row < NP)      v = *reinterpret_cast<const float4*>(prox + base);
        else if (row < NN) v = *reinterpret_cast<const float4*>(x + base - NP * D);
    }

    // split store
    __nv_bfloat16 h0 = __float2bfloat16(v.x), h1 = __float2bfloat16(v.y);
    __nv_bfloat16 h2 = __float2bfloat16(v.z), h3 = __float2bfloat16(v.w);
    *reinterpret_cast<__nv_bfloat162*>(g_Ah + base)     = __nv_bfloat162(h0, h1);
    *reinterpret_cast<__nv_bfloat162*>(g_Ah + base + 2) = __nv_bfloat162(h2, h3);
    *reinterpret_cast<__nv_bfloat162*>(g_Al + base) =
        __nv_bfloat162(__float2bfloat16(v.x - __bfloat162float(h0)),
                       __float2bfloat16(v.y - __bfloat162float(h1)));
    *reinterpret_cast<__nv_bfloat162*>(g_Al + base + 2) =
        __nv_bfloat162(__float2bfloat16(v.z - __bfloat162float(h2)),
                       __float2bfloat16(v.w - __bfloat162float(h3)));

    if (row >= NN) return;

    // logits: dot row with v[vbase], v[vbase+1]
    float4 vs = *reinterpret_cast<const float4*>(&g_v[vbase][tid * 4]);
    float4 vd = *reinterpret_cast<const float4*>(&g_v[vbase + 1][tid * 4]);
    float s = v.x * vs.x + v.y * vs.y + v.z * vs.z + v.w * vs.w;
    float t = v.x * vd.x + v.y * vd.y + v.z * vd.z + v.w * vd.w;
    #pragma unroll
    for (int o = 16; o > 0; o >>= 1) {
        s += __shfl_xor_sync(0xffffffffu, s, o);
        t += __shfl_xor_sync(0xffffffffu, t, o);
    }
    if ((tid & 31) == 0) { sh[tid >> 5] = s; sh[4 + (tid >> 5)] = t; }
    __syncthreads();
    if (tid == 0) g_lsrc[row] = sh[0] + sh[1] + sh[2] + sh[3];
    if (tid == 32) g_ldst[row] = sh[4] + sh[5] + sh[6] + sh[7];
}

// ============================ tensor-core GEMM: g_HW = A @ W ============================
#define SWB(r, b) ((r) * 128 + ((b) ^ (((r) & 7) << 4)))

__device__ __forceinline__ void ldm_x4(uint32_t* f, uint32_t addr) {
    asm volatile("ldmatrix.sync.aligned.m8n8.x4.shared.b16 {%0,%1,%2,%3}, [%4];"
                 : "=r"(f[0]), "=r"(f[1]), "=r"(f[2]), "=r"(f[3]) : "r"(addr));
}
__device__ __forceinline__ void ldm_x2(uint32_t* f, uint32_t addr) {
    asm volatile("ldmatrix.sync.aligned.m8n8.x2.shared.b16 {%0,%1}, [%2];"
                 : "=r"(f[0]), "=r"(f[1]) : "r"(addr));
}
__device__ __forceinline__ void mma_bf16(float* c, const uint32_t* a, const uint32_t* b) {
    asm volatile(
        "mma.sync.aligned.m16n8k16.row.col.f32.bf16.bf16.f32 "
        "{%0,%1,%2,%3}, {%4,%5,%6,%7}, {%8,%9}, {%0,%1,%2,%3};"
        : "+f"(c[0]), "+f"(c[1]), "+f"(c[2]), "+f"(c[3])
        : "r"(a[0]), "r"(a[1]), "r"(a[2]), "r"(a[3]), "r"(b[0]), "r"(b[1]));
}

__global__ void __launch_bounds__(256, 1) k_mma_gemm(const __nv_bfloat16* __restrict__ Wh,
                                                     const __nv_bfloat16* __restrict__ Wl) {
    __shared__ __align__(16) char sm[32768];   // Ah 8K | Al 8K | Bh 8K | Bl 8K
    int tid = threadIdx.x, wid = tid >> 5, lane = tid & 31;
    int n0 = blockIdx.x * 64, m0 = blockIdx.y * 64;
    int wm = (wid >> 2) * 32, wn = (wid & 3) * 16;

    uint32_t sb = smem_u32(sm);

    int a_r = (lane & 7) + ((lane >> 3) & 1) * 8;
    int a_kb = (lane >> 4) * 16;
    int b_r = lane & 7;
    int b_kb = ((lane >> 3) & 1) * 16;

    float acc[2][2][4] = {};

    for (int c = 0; c < D / 64; c++) {
        int kc = c * 64;
        #pragma unroll
        for (int o = 0; o < 4; o++) {
            const __nv_bfloat16* src;
            int rbase;
            if (o == 0)      { src = g_Ah; rbase = m0; }
            else if (o == 1) { src = g_Al; rbase = m0; }
            else if (o == 2) { src = Wh;   rbase = n0; }
            else             { src = Wl;   rbase = n0; }
            char* dst = sm + o * 8192;
            #pragma unroll
            for (int q = 0; q < 2; q++) {
                int i = tid * 2 + q;
                int r = i >> 3, s = i & 7;
                uint4 v = *reinterpret_cast<const uint4*>(src + (size_t)(rbase + r) * D + kc + s * 8);
                *reinterpret_cast<uint4*>(dst + SWB(r, s * 16)) = v;
            }
        }
        __syncthreads();

        #pragma unroll
        for (int ks = 0; ks < 4; ks++) {
            int kb = ks * 32;
            uint32_t ah[2][4], al[2][4], bh[2][2], bl[2][2];
            #pragma unroll
            for (int mt = 0; mt < 2; mt++) {
                int r = wm + mt * 16 + a_r;
                ldm_x4(ah[mt], sb + 0    + SWB(r, kb + a_kb));
                ldm_x4(al[mt], sb + 8192 + SWB(r, kb + a_kb));
            }
            #pragma unroll
            for (int nt = 0; nt < 2; nt++) {
                int r = wn + nt * 8 + b_r;
                ldm_x2(bh[nt], sb + 16384 + SWB(r, kb + b_kb));
                ldm_x2(bl[nt], sb + 24576 + SWB(r, kb + b_kb));
            }
            #pragma unroll
            for (int mt = 0; mt < 2; mt++)
                #pragma unroll
                for (int nt = 0; nt < 2; nt++) {
                    mma_bf16(acc[mt][nt], ah[mt], bh[nt]);
                    mma_bf16(acc[mt][nt], ah[mt], bl[nt]);
                    mma_bf16(acc[mt][nt], al[mt], bh[nt]);
                }
        }
        __syncthreads();
    }

    #pragma unroll
    for (int mt = 0; mt < 2; mt++) {
        int row = m0 + wm + mt * 16 + (lane >> 2);
        #pragma unroll
        for (int nt = 0; nt < 2; nt++) {
            int col = n0 + wn + nt * 8 + (lane & 3) * 2;
            if (row < NN)
                *reinterpret_cast<float2*>(g_HW + (size_t)row * D + col) =
                    make_float2(acc[mt][nt][0], acc[mt][nt][1]);
            if (row + 8 < NN)
                *reinterpret_cast<float2*>(g_HW + (size_t)(row + 8) * D + col) =
                    make_float2(acc[mt][nt][2], acc[mt][nt][3]);
        }
    }
}

// ============================ fused alpha (samples + proxies) ============================
// blocks 0..127: 8 warps, one sample each. blocks 128..227: one proxy each.
__global__ void k_alpha() {
    int tid = threadIdx.x;
    if (blockIdx.x < 128) {
        int warp = blockIdx.x * 8 + (tid >> 5);
        int lane = tid & 31;
        int node = NP + warp;
        float ld = g_ldst[node];
        float e[4];
        #pragma unroll
        for (int i = 0; i < 4; i++) {
            int p = lane + 32 * i;
            e[i] = (p < NP) ? lrelu(g_lsrc[p] + ld) : -1e30f;
        }
        float eself = lrelu(g_lsrc[node] + ld);

        float m = fmaxf(fmaxf(e[0], e[1]), fmaxf(e[2], e[3]));
        #pragma unroll
        for (int o = 16; o > 0; o >>= 1) m = fmaxf(m, __shfl_xor_sync(0xffffffffu, m, o));
        m = fmaxf(m, eself);

        float w[4], sum = 0.f;
        #pragma unroll
        for (int i = 0; i < 4; i++) {
            int p = lane + 32 * i;
            w[i] = (p < NP) ? expf(e[i] - m) : 0.f;
            sum += w[i];
        }
        #pragma unroll
        for (int o = 16; o > 0; o >>= 1) sum += __shfl_xor_sync(0xffffffffu, sum, o);
        float wself = expf(eself - m);
        float inv = 1.f / (sum + wself);

        #pragma unroll
        for (int i = 0; i < 4; i++) {
            int p = lane + 32 * i;
            if (p < KPAD) g_alphaS[(size_t)warp * KPAD + p] = w[i] * inv;
        }
        if (lane == 0) g_aselfS[warp] = wself * inv;
    } else {
        __shared__ float sh[8];
        __shared__ float s_m, s_inv;
        int p = blockIdx.x - 128;
        float ld = g_ldst[p];

        float e[4];
        float m = -1e30f;
        #pragma unroll
        for (int i = 0; i < 4; i++) {
            int s = tid + i * 256;
            e[i] = lrelu(g_lsrc[NP + s] + ld);
            m = fmaxf(m, e[i]);
        }
        float eself = lrelu(g_lsrc[p] + ld);

        #pragma unroll
        for (int o = 16; o > 0; o >>= 1) m = fmaxf(m, __shfl_xor_sync(0xffffffffu, m, o));
        if ((tid & 31) == 0) sh[tid >> 5] = m;
        __syncthreads();
        if (tid == 0) {
            float mm = sh[0];
            #pragma unroll
            for (int i = 1; i < 8; i++) mm = fmaxf(mm, sh[i]);
            s_m = fmaxf(mm, eself);
        }
        __syncthreads();
        m = s_m;

        float w[4], sum = 0.f;
        #pragma unroll
        for (int i = 0; i < 4; i++) { w[i] = expf(e[i] - m); sum += w[i]; }
        #pragma unroll
        for (int o = 16; o > 0; o >>= 1) sum += __shfl_xor_sync(0xffffffffu, sum, o);
        if ((tid & 31) == 0) sh[tid >> 5] = sum;
        __syncthreads();
        if (tid == 0) {
            float ss = 0.f;
            #pragma unroll
            for (int i = 0; i < 8; i++) ss += sh[i];
            s_inv = 1.f / (ss + expf(eself - m));
        }
        __syncthreads();
        float inv = s_inv;

        #pragma unroll
        for (int i = 0; i < 4; i++)
            g_alphaP[(size_t)p * NS + tid + i * 256] = w[i] * inv;
        if (tid == 0) g_aselfP[p] = expf(eself - m) * inv;
    }
}

// ============================ fused aggregation GEMMs ============================
// blocks 0..127: sample aggregation (bx=b&7 ntile, by=b>>3 mtile).
// blocks 128..255: proxy split-K partials.
// hout != null (layer 2): also write relu result rows to hout (the h output region).
#define BM 64
#define BN 64
#define BK 16
__global__ void k_agg(const float* __restrict__ HW, const float* __restrict__ bias,
                      float* __restrict__ out, float* __restrict__ hout) {
    __shared__ float As[BK][BM];
    __shared__ float Bs[BK][BN];
    int tid = threadIdx.x;
    int tx = tid & 15, ty = tid >> 4;
    int la = tid * 4;
    int ar = la >> 4, ac = la & 15;
    int br = la >> 6, bc = la & 63;
    float acc[4][4] = {};

    if (blockIdx.x < 128) {
        int m0 = (blockIdx.x >> 3) * BM, n0 = (blockIdx.x & 7) * BN;
        #pragma unroll
        for (int k0 = 0; k0 < KPAD; k0 += BK) {
            float4 av = *reinterpret_cast<const float4*>(g_alphaS + (size_t)(m0 + ar) * KPAD + k0 + ac);
            As[ac + 0][ar] = av.x; As[ac + 1][ar] = av.y;
            As[ac + 2][ar] = av.z; As[ac + 3][ar] = av.w;
            float4 bv = *reinterpret_cast<const float4*>(HW + (size_t)(k0 + br) * D + n0 + bc);
            *reinterpret_cast<float4*>(&Bs[br][bc]) = bv;
            __syncthreads();
            #pragma unroll
            for (int kk = 0; kk < BK; kk++) {
                float a0 = As[kk][ty * 4 + 0], a1 = As[kk][ty * 4 + 1];
                float a2 = As[kk][ty * 4 + 2], a3 = As[kk][ty * 4 + 3];
                float b0 = Bs[kk][tx * 4 + 0], b1 = Bs[kk][tx * 4 + 1];
                float b2 = Bs[kk][tx * 4 + 2], b3 = Bs[kk][tx * 4 + 3];
                acc[0][0] += a0 * b0; acc[0][1] += a0 * b1; acc[0][2] += a0 * b2; acc[0][3] += a0 * b3;
                acc[1][0] += a1 * b0; acc[1][1] += a1 * b1; acc[1][2] += a1 * b2; acc[1][3] += a1 * b3;
                acc[2][0] += a2 * b0; acc[2][1] += a2 * b1; acc[2][2] += a2 * b2; acc[2][3] += a2 * b3;
                acc[3][0] += a3 * b0; acc[3][1] += a3 * b1; acc[3][2] += a3 * b2; acc[3][3] += a3 * b3;
            }
            __syncthreads();
        }
        #pragma unroll
        for (int i = 0; i < 4; i++) {
            int r = m0 + ty * 4 + i;
            float aself = g_aselfS[r];
            #pragma unroll
            for (int j = 0; j < 4; j++) {
                int c = n0 + tx * 4 + j;
                float v = acc[i][j] + aself * HW[(size_t)(NP + r) * D + c] + bias[c];
                v = v > 0.f ? v : 0.f;
                out[(size_t)(NP + r) * D + c] = v;
                if (hout) hout[(size_t)r * D + c] = v;
            }
        }
    } else {
        int b = blockIdx.x - 128;            // (8 ntiles, 2 mtiles, 8 splits)
        int n0 = (b & 7) * BN;
        int m0 = ((b >> 3) & 1) * BM;
        int z = b >> 4;
        int kbase = z * (NS / SPLITK);
        #pragma unroll
        for (int kk0 = 0; kk0 < NS / SPLITK; kk0 += BK) {
            int k0 = kbase + kk0;
            float4 av = make_float4(0.f, 0.f, 0.f, 0.f);
            if (m0 + ar < NP)
                av = *reinterpret_cast<const float4*>(g_alphaP + (size_t)(m0 + ar) * NS + k0 + ac);
            As[ac + 0][ar] = av.x; As[ac + 1][ar] = av.y;
            As[ac + 2][ar] = av.z; As[ac + 3][ar] = av.w;
            float4 bv = *reinterpret_cast<const float4*>(HW + (size_t)(NP + k0 + br) * D + n0 + bc);
            *reinterpret_cast<float4*>(&Bs[br][bc]) = bv;
            __syncthreads();
            #pragma unroll
            for (int kk = 0; kk < BK; kk++) {
                float a0 = As[kk][ty * 4 + 0], a1 = As[kk][ty * 4 + 1];
                float a2 = As[kk][ty * 4 + 2], a3 = As[kk][ty * 4 + 3];
                float b0 = Bs[kk][tx * 4 + 0], b1 = Bs[kk][tx * 4 + 1];
                float b2 = Bs[kk][tx * 4 + 2], b3 = Bs[kk][tx * 4 + 3];
                acc[0][0] += a0 * b0; acc[0][1] += a0 * b1; acc[0][2] += a0 * b2; acc[0][3] += a0 * b3;
                acc[1][0] += a1 * b0; acc[1][1] += a1 * b1; acc[1][2] += a1 * b2; acc[1][3] += a1 * b3;
                acc[2][0] += a2 * b0; acc[2][1] += a2 * b1; acc[2][2] += a2 * b2; acc[2][3] += a2 * b3;
                acc[3][0] += a3 * b0; acc[3][1] += a3 * b1; acc[3][2] += a3 * b2; acc[3][3] += a3 * b3;
            }
            __syncthreads();
        }
        float* part = g_ppart + (size_t)z * NP * D;
        #pragma unroll
        for (int i = 0; i < 4; i++) {
            int r = m0 + ty * 4 + i;
            if (r >= NP) continue;
            #pragma unroll
            for (int j = 0; j < 4; j++)
                part[(size_t)r * D + n0 + tx * 4 + j] = acc[i][j];
        }
    }
}

__global__ void k_prox_fin(const float* __restrict__ HW,
                           const float* __restrict__ bias,
                           float* __restrict__ out) {
    int idx = blockIdx.x * blockDim.x + threadIdx.x;
    if (idx >= NP * D) return;
    int p = idx / D, c = idx - p * D;
    float v = 0.f;
    #pragma unroll
    for (int z = 0; z < SPLITK; z++) v += g_ppart[(size_t)z * NP * D + idx];
    v += g_aselfP[p] * HW[(size_t)p * D + c] + bias[c];
    out[(size_t)p * D + c] = v > 0.f ? v : 0.f;
}

// ============================ fp32 GEMM (FC head) ============================
__global__ void k_gemm(const float* __restrict__ A, const float* __restrict__ B,
                       float* __restrict__ C, int M, int N, int K,
                       const float* __restrict__ bias) {
    __shared__ float As[BK][BM];
    __shared__ float Bs[BK][BN];
    int tid = threadIdx.x;
    int tx = tid & 15, ty = tid >> 4;
    int m0 = blockIdx.y * BM, n0 = blockIdx.x * BN;
    int la = tid * 4;
    int ar = la >> 4, ac = la & 15;
    int br = la >> 6, bc = la & 63;
    float acc[4][4] = {};

    for (int k0 = 0; k0 < K; k0 += BK) {
        float4 av = make_float4(0.f, 0.f, 0.f, 0.f);
        if (m0 + ar < M)
            av = *reinterpret_cast<const float4*>(A + (size_t)(m0 + ar) * K + k0 + ac);
        As[ac + 0][ar] = av.x; As[ac + 1][ar] = av.y;
        As[ac + 2][ar] = av.z; As[ac + 3][ar] = av.w;

        float4 bv = make_float4(0.f, 0.f, 0.f, 0.f);
        {
            const float* brow = B + (size_t)(k0 + br) * N;
            int gc = n0 + bc;
            if (gc + 3 < N) bv = *reinterpret_cast<const float4*>(brow + gc);
            else {
                if (gc + 0 < N) bv.x = brow[gc + 0];
                if (gc + 1 < N) bv.y = brow[gc + 1];
                if (gc + 2 < N) bv.z = brow[gc + 2];
            }
        }
        *reinterpret_cast<float4*>(&Bs[br][bc]) = bv;
        __syncthreads();

        #pragma unroll
        for (int kk = 0; kk < BK; kk++) {
            float a0 = As[kk][ty * 4 + 0], a1 = As[kk][ty * 4 + 1];
            float a2 = As[kk][ty * 4 + 2], a3 = As[kk][ty * 4 + 3];
            float b0 = Bs[kk][tx * 4 + 0], b1 = Bs[kk][tx * 4 + 1];
            float b2 = Bs[kk][tx * 4 + 2], b3 = Bs[kk][tx * 4 + 3];
            acc[0][0] += a0 * b0; acc[0][1] += a0 * b1; acc[0][2] += a0 * b2; acc[0][3] += a0 * b3;
            acc[1][0] += a1 * b0; acc[1][1] += a1 * b1; acc[1][2] += a1 * b2; acc[1][3] += a1 * b3;
            acc[2][0] += a2 * b0; acc[2][1] += a2 * b1; acc[2][2] += a2 * b2; acc[2][3] += a2 * b3;
            acc[3][0] += a3 * b0; acc[3][1] += a3 * b1; acc[3][2] += a3 * b2; acc[3][3] += a3 * b3;
        }
        __syncthreads();
    }

    #pragma unroll
    for (int i = 0; i < 4; i++) {
        int r = m0 + ty * 4 + i;
        if (r >= M) continue;
        #pragma unroll
        for (int j = 0; j < 4; j++) {
            int c = n0 + tx * 4 + j;
            if (c >= N) continue;
            float v = acc[i][j];
            if (bias) v += bias[c];
            C[(size_t)r * N + c] = v;
        }
    }
}

// ============================ launch ============================
extern "C" void kernel_launch(void* const* d_in, const int* in_sizes, int n_in,
                              void* d_out, int out_size) {
    const float* x    = (const float*)d_in[0];
    const float* prox = (const float*)d_in[1];
    const float* W1   = (const float*)d_in[2];
    const float* as1  = (const float*)d_in[3];
    const float* ad1  = (const float*)d_in[4];
    const float* b1   = (const float*)d_in[5];
    const float* W2   = (const float*)d_in[6];
    const float* as2  = (const float*)d_in[7];
    const float* ad2  = (const float*)d_in[8];
    const float* b2   = (const float*)d_in[9];
    const float* fcw  = (const float*)d_in[10];
    const float* fcb  = (const float*)d_in[11];
    float* out = (float*)d_out;

    float *pA, *pHW, *pB;
    __nv_bfloat16 *pW1h, *pW1l, *pW2h, *pW2l;
    cudaGetSymbolAddress((void**)&pA,  g_A);
    cudaGetSymbolAddress((void**)&pHW, g_HW);
    cudaGetSymbolAddress((void**)&pB,  g_B);
    cudaGetSymbolAddress((void**)&pW1h, g_W1h);
    cudaGetSymbolAddress((void**)&pW1l, g_W1l);
    cudaGetSymbolAddress((void**)&pW2h, g_W2h);
    cudaGetSymbolAddress((void**)&pW2l, g_W2l);

    dim3 mma_grid(D / 64, MPAD / 64);   // (8, 18)

    // prep: both W transposes + 4 matvecs
    k_prep<<<dim3(16, 16, 3), 256>>>(W1, W2, as1, ad1, as2, ad2);

    // ---- layer 1
    k_cvt_log<<<MPAD, 128>>>(x, prox, nullptr, 0);
    k_mma_gemm<<<mma_grid, 256>>>(pW1h, pW1l);
    k_alpha<<<228, 256>>>();
    k_agg<<<256, 256>>>(pHW, b1, pB, nullptr);
    k_prox_fin<<<(NP * D + 255) / 256, 256>>>(pHW, b1, pB);

    // ---- layer 2 (proxy outputs unused downstream -> samples only)
    k_cvt_log<<<MPAD, 128>>>(nullptr, nullptr, pB, 2);
    k_mma_gemm<<<mma_grid, 256>>>(pW2h, pW2l);
    k_alpha<<<128, 256>>>();
    k_agg<<<128, 256>>>(pHW, b2, pA, out + NS * 100);   // also writes h output

    // ---- preds = h @ fc_w + fc_b
    dim3 fc_grid(2, NS / BM);   // (2, 16)
    k_gemm<<<fc_grid, 256>>>(pA + NP * D, fcw, out, NS, 100, D, fcb);
}

// round 6
// speedup vs baseline: 3.8457x; 1.4234x over previous
#include <cuda_runtime.h>
#include <cuda_bf16.h>
#include <cstdint>

#define NP 100      // proxies
#define NS 1024     // samples
#define NN 1124     // total nodes
#define MPAD 1152   // NN padded to 128
#define D  512
#define KPAD 112    // NP padded to multiple of 16
#define SPLITK 8    // split-K parts for proxy aggregation

// scratch (device globals; no allocation allowed)
__device__ float g_HW[NN * D];
__device__ float g_lsrc[NN];
__device__ float g_ldst[NN];
__device__ float g_alphaS[NS * KPAD];
__device__ float g_aselfS[NS];
__device__ float g_alphaP[NP * NS];
__device__ float g_aselfP[NP];
__device__ float g_ppart[SPLITK * NP * D];
__device__ float g_v[4][D];             // W1@as1, W1@ad1, W2@as2, W2@ad2
__device__ float g_lp[8][NN][2];        // layer-2 logit partials [ntile][node][src/dst]
// bf16 split operands for tensor-core GEMMs
__device__ __nv_bfloat16 g_Ah[MPAD * D];
__device__ __nv_bfloat16 g_Al[MPAD * D];
__device__ __nv_bfloat16 g_W1h[D * D];  // transposed [N,K]
__device__ __nv_bfloat16 g_W1l[D * D];
__device__ __nv_bfloat16 g_W2h[D * D];
__device__ __nv_bfloat16 g_W2l[D * D];
__device__ __nv_bfloat16 g_FCh[128 * D]; // fc_w transposed [100->128, 512]
__device__ __nv_bfloat16 g_FCl[128 * D];

__device__ __forceinline__ float lrelu(float v) { return v > 0.f ? v : 0.2f * v; }

__device__ __forceinline__ uint32_t smem_u32(const void* p) {
    uint32_t a;
    asm("{ .reg .u64 t; cvta.to.shared.u64 t, %1; cvt.u32.u64 %0, t; }" : "=r"(a) : "l"(p));
    return a;
}

// ============================ prep ============================
// grid (16,16,4): z=0 W1 transpose/split, z=1 W2, z=2 matvecs, z=3 fcw transpose/split
__global__ void k_prep(const float* __restrict__ W1, const float* __restrict__ W2,
                       const float* __restrict__ fcw,
                       const float* __restrict__ as1, const float* __restrict__ ad1,
                       const float* __restrict__ as2, const float* __restrict__ ad2) {
    if (blockIdx.z < 2) {
        const float* W = blockIdx.z ? W2 : W1;
        __nv_bfloat16* Wh = blockIdx.z ? g_W2h : g_W1h;
        __nv_bfloat16* Wl = blockIdx.z ? g_W2l : g_W1l;
        __shared__ float t[32][33];
        int tx = threadIdx.x & 31, ty = threadIdx.x >> 5;
        int k0 = blockIdx.y * 32, n0 = blockIdx.x * 32;
        #pragma unroll
        for (int j = 0; j < 4; j++)
            t[ty + 8 * j][tx] = W[(size_t)(k0 + ty + 8 * j) * D + n0 + tx];
        __syncthreads();
        #pragma unroll
        for (int j = 0; j < 4; j++) {
            int n = n0 + ty + 8 * j, k = k0 + tx;
            float v = t[tx][ty + 8 * j];
            __nv_bfloat16 hi = __float2bfloat16(v);
            Wh[(size_t)n * D + k] = hi;
            Wl[(size_t)n * D + k] = __float2bfloat16(v - __bfloat162float(hi));
        }
    } else if (blockIdx.z == 2) {
        // 4 matvecs W@a: 2048 warps
        int b = blockIdx.y * 16 + blockIdx.x;
        int gw = b * 8 + (threadIdx.x >> 5);
        int lane = threadIdx.x & 31;
        int vec = gw >> 9, k = gw & 511;
        const float* W = (vec < 2) ? W1 : W2;
        const float* a = (vec == 0) ? as1 : (vec == 1) ? ad1 : (vec == 2) ? as2 : ad2;
        const float* wr = W + (size_t)k * D;
        float s = 0.f;
        #pragma unroll 4
        for (int n = lane; n < D; n += 32) s += wr[n] * a[n];
        #pragma unroll
        for (int o = 16; o > 0; o >>= 1) s += __shfl_xor_sync(0xffffffffu, s, o);
        if (lane == 0) g_v[vec][k] = s;
    } else {
        // fcw [512,100] -> [128,512] transposed split (rows >= 100 zero)
        if (blockIdx.x >= 4) return;
        __shared__ float t[32][33];
        int tx = threadIdx.x & 31, ty = threadIdx.x >> 5;
        int k0 = blockIdx.y * 32, n0 = blockIdx.x * 32;
        #pragma unroll
        for (int j = 0; j < 4; j++) {
            int n = n0 + tx;
            t[ty + 8 * j][tx] = (n < 100) ? fcw[(size_t)(k0 + ty + 8 * j) * 100 + n] : 0.f;
        }
        __syncthreads();
        #pragma unroll
        for (int j = 0; j < 4; j++) {
            int n = n0 + ty + 8 * j, k = k0 + tx;
            float v = t[tx][ty + 8 * j];
            __nv_bfloat16 hi = __float2bfloat16(v);
            g_FCh[(size_t)n * D + k] = hi;
            g_FCl[(size_t)n * D + k] = __float2bfloat16(v - __bfloat162float(hi));
        }
    }
}

// ============================ layer-1 convert + logits ============================
__global__ void k_cvt_log(const float* __restrict__ x, const float* __restrict__ prox) {
    __shared__ float sh[8];
    int row = blockIdx.x, tid = threadIdx.x;
    int base = row * D + tid * 4;

    float4 v = make_float4(0.f, 0.f, 0.f, 0.f);
    if (row < NP)      v = *reinterpret_cast<const float4*>(prox + base);
    else if (row < NN) v = *reinterpret_cast<const float4*>(x + base - NP * D);

    __nv_bfloat16 h0 = __float2bfloat16(v.x), h1 = __float2bfloat16(v.y);
    __nv_bfloat16 h2 = __float2bfloat16(v.z), h3 = __float2bfloat16(v.w);
    *reinterpret_cast<__nv_bfloat162*>(g_Ah + base)     = __nv_bfloat162(h0, h1);
    *reinterpret_cast<__nv_bfloat162*>(g_Ah + base + 2) = __nv_bfloat162(h2, h3);
    *reinterpret_cast<__nv_bfloat162*>(g_Al + base) =
        __nv_bfloat162(__float2bfloat16(v.x - __bfloat162float(h0)),
                       __float2bfloat16(v.y - __bfloat162float(h1)));
    *reinterpret_cast<__nv_bfloat162*>(g_Al + base + 2) =
        __nv_bfloat162(__float2bfloat16(v.z - __bfloat162float(h2)),
                       __float2bfloat16(v.w - __bfloat162float(h3)));

    if (row >= NN) return;

    float4 vs = *reinterpret_cast<const float4*>(&g_v[0][tid * 4]);
    float4 vd = *reinterpret_cast<const float4*>(&g_v[1][tid * 4]);
    float s = v.x * vs.x + v.y * vs.y + v.z * vs.z + v.w * vs.w;
    float t = v.x * vd.x + v.y * vd.y + v.z * vd.z + v.w * vd.w;
    #pragma unroll
    for (int o = 16; o > 0; o >>= 1) {
        s += __shfl_xor_sync(0xffffffffu, s, o);
        t += __shfl_xor_sync(0xffffffffu, t, o);
    }
    if ((tid & 31) == 0) { sh[tid >> 5] = s; sh[4 + (tid >> 5)] = t; }
    __syncthreads();
    if (tid == 0) g_lsrc[row] = sh[0] + sh[1] + sh[2] + sh[3];
    if (tid == 32) g_ldst[row] = sh[4] + sh[5] + sh[6] + sh[7];
}

// ============================ generic bf16-split tensor-core GEMM ============================
// 64x64 tile, 8 warps (2m x 4n), BK=64, cp.async double-buffered. K fixed = 512.
#define SWB(r, b) ((r) * 128 + ((b) ^ (((r) & 7) << 4)))
#define STAGE_BYTES 32768

__device__ __forceinline__ void ldm_x4(uint32_t* f, uint32_t addr) {
    asm volatile("ldmatrix.sync.aligned.m8n8.x4.shared.b16 {%0,%1,%2,%3}, [%4];"
                 : "=r"(f[0]), "=r"(f[1]), "=r"(f[2]), "=r"(f[3]) : "r"(addr));
}
__device__ __forceinline__ void ldm_x2(uint32_t* f, uint32_t addr) {
    asm volatile("ldmatrix.sync.aligned.m8n8.x2.shared.b16 {%0,%1}, [%2];"
                 : "=r"(f[0]), "=r"(f[1]) : "r"(addr));
}
__device__ __forceinline__ void mma_bf16(float* c, const uint32_t* a, const uint32_t* b) {
    asm volatile(
        "mma.sync.aligned.m16n8k16.row.col.f32.bf16.bf16.f32 "
        "{%0,%1,%2,%3}, {%4,%5,%6,%7}, {%8,%9}, {%0,%1,%2,%3};"
        : "+f"(c[0]), "+f"(c[1]), "+f"(c[2]), "+f"(c[3])
        : "r"(a[0]), "r"(a[1]), "r"(a[2]), "r"(a[3]), "r"(b[0]), "r"(b[1]));
}
__device__ __forceinline__ void cpa16(uint32_t saddr, const void* g) {
    asm volatile("cp.async.cg.shared.global [%0], [%1], 16;" :: "r"(saddr), "l"(g));
}

__global__ void __launch_bounds__(256, 1) k_mma(
    const __nv_bfloat16* __restrict__ Ah, const __nv_bfloat16* __restrict__ Al,
    const __nv_bfloat16* __restrict__ Bh, const __nv_bfloat16* __restrict__ Bl,
    float* __restrict__ C, int ldc, int rmax, int cmax, const float* __restrict__ bias) {
    extern __shared__ __align__(16) char sm[];   // 2 x 32KB stages
    int tid = threadIdx.x, wid = tid >> 5, lane = tid & 31;
    int n0 = blockIdx.x * 64, m0 = blockIdx.y * 64;
    int wm = (wid >> 2) * 32, wn = (wid & 3) * 16;
    uint32_t sb = smem_u32(sm);

    int li = tid * 2;                 // two 16B slots per thread per operand
    int lr0 = li >> 3, ls0 = li & 7;
    int lr1 = (li + 1) >> 3, ls1 = (li + 1) & 7;

    int a_r = (lane & 7) + ((lane >> 3) & 1) * 8;
    int a_kb = (lane >> 4) * 16;
    int b_r = lane & 7;
    int b_kb = ((lane >> 3) & 1) * 16;

    float acc[2][2][4] = {};

    const __nv_bfloat16* srcs[4] = { Ah, Al, Bh, Bl };
    int rbases[4] = { m0, m0, n0, n0 };

    // issue chunk c into stage st
    auto issue = [&](int c, int st) {
        int kc = c * 64;
        uint32_t stb = sb + st * STAGE_BYTES;
        #pragma unroll
        for (int o = 0; o < 4; o++) {
            const __nv_bfloat16* s = srcs[o];
            int rb = rbases[o];
            cpa16(stb + o * 8192 + SWB(lr0, ls0 * 16), s + (size_t)(rb + lr0) * D + kc + ls0 * 8);
            cpa16(stb + o * 8192 + SWB(lr1, ls1 * 16), s + (size_t)(rb + lr1) * D + kc + ls1 * 8);
        }
        asm volatile("cp.async.commit_group;");
    };

    issue(0, 0);
    asm volatile("cp.async.wait_group 0;");
    __syncthreads();

    for (int c = 0; c < 8; c++) {
        int st = c & 1;
        if (c < 7) issue(c + 1, st ^ 1);
        uint32_t stb = sb + st * STAGE_BYTES;

        #pragma unroll
        for (int ks = 0; ks < 4; ks++) {
            int kb = ks * 32;
            uint32_t ah[2][4], al[2][4], bh[2][2], bl[2][2];
            #pragma unroll
            for (int mt = 0; mt < 2; mt++) {
                int r = wm + mt * 16 + a_r;
                ldm_x4(ah[mt], stb + 0    + SWB(r, kb + a_kb));
                ldm_x4(al[mt], stb + 8192 + SWB(r, kb + a_kb));
            }
            #pragma unroll
            for (int nt = 0; nt < 2; nt++) {
                int r = wn + nt * 8 + b_r;
                ldm_x2(bh[nt], stb + 16384 + SWB(r, kb + b_kb));
                ldm_x2(bl[nt], stb + 24576 + SWB(r, kb + b_kb));
            }
            #pragma unroll
            for (int mt = 0; mt < 2; mt++)
                #pragma unroll
                for (int nt = 0; nt < 2; nt++) {
                    mma_bf16(acc[mt][nt], ah[mt], bh[nt]);
                    mma_bf16(acc[mt][nt], ah[mt], bl[nt]);
                    mma_bf16(acc[mt][nt], al[mt], bh[nt]);
                }
        }
        if (c < 7) asm volatile("cp.async.wait_group 0;");
        __syncthreads();
    }

    #pragma unroll
    for (int mt = 0; mt < 2; mt++) {
        int row = m0 + wm + mt * 16 + (lane >> 2);
        #pragma unroll
        for (int nt = 0; nt < 2; nt++) {
            int col = n0 + wn + nt * 8 + (lane & 3) * 2;
            if (col >= cmax) continue;
            float b0 = bias ? bias[col] : 0.f;
            float b1 = bias ? bias[col + 1] : 0.f;
            if (row < rmax)
                *reinterpret_cast<float2*>(C + (size_t)row * ldc + col) =
                    make_float2(acc[mt][nt][0] + b0, acc[mt][nt][1] + b1);
            if (row + 8 < rmax)
                *reinterpret_cast<float2*>(C + (size_t)(row + 8) * ldc + col) =
                    make_float2(acc[mt][nt][2] + b0, acc[mt][nt][3] + b1);
        }
    }
}

// ============================ alpha (no max subtraction) ============================
// blocks 0..127: 8 warps, one sample each. blocks 128..227: one proxy each (layer 1 only).
__global__ void k_alpha(const float* __restrict__ lsrc, const float* __restrict__ ldst,
                        int zero_lp) {
    int tid = threadIdx.x;
    if (zero_lp && blockIdx.x == 0) {
        float* lp = &g_lp[0][0][0];
        for (int i = tid; i < 8 * NN * 2; i += 256) lp[i] = 0.f;
    }
    if (blockIdx.x < 128) {
        int warp = blockIdx.x * 8 + (tid >> 5);
        int lane = tid & 31;
        int node = NP + warp;
        float ld = ldst[node];
        float w[4], sum = 0.f;
        #pragma unroll
        for (int i = 0; i < 4; i++) {
            int p = lane + 32 * i;
            w[i] = (p < NP) ? __expf(lrelu(lsrc[p] + ld)) : 0.f;
            sum += w[i];
        }
        float wself = __expf(lrelu(lsrc[node] + ld));
        #pragma unroll
        for (int o = 16; o > 0; o >>= 1) sum += __shfl_xor_sync(0xffffffffu, sum, o);
        float inv = 1.f / (sum + wself);
        #pragma unroll
        for (int i = 0; i < 4; i++) {
            int p = lane + 32 * i;
            if (p < KPAD) g_alphaS[(size_t)warp * KPAD + p] = w[i] * inv;
        }
        if (lane == 0) g_aselfS[warp] = wself * inv;
    } else {
        __shared__ float sh[8];
        __shared__ float s_inv;
        int p = blockIdx.x - 128;
        float ld = ldst[p];
        float w[4], sum = 0.f;
        #pragma unroll
        for (int i = 0; i < 4; i++) {
            w[i] = __expf(lrelu(lsrc[NP + tid + i * 256] + ld));
            sum += w[i];
        }
        float wself = __expf(lrelu(lsrc[p] + ld));
        #pragma unroll
        for (int o = 16; o > 0; o >>= 1) sum += __shfl_xor_sync(0xffffffffu, sum, o);
        if ((tid & 31) == 0) sh[tid >> 5] = sum;
        __syncthreads();
        if (tid == 0) {
            float ss = 0.f;
            #pragma unroll
            for (int i = 0; i < 8; i++) ss += sh[i];
            s_inv = 1.f / (ss + wself);
        }
        __syncthreads();
        float inv = s_inv;
        #pragma unroll
        for (int i = 0; i < 4; i++)
            g_alphaP[(size_t)p * NS + tid + i * 256] = w[i] * inv;
        if (tid == 0) g_aselfP[p] = wself * inv;
    }
}

// ============================ fused aggregation ============================
// blocks <128: sample aggregation; blocks 128..255: proxy split-K partials (layer 1 only).
// layer==1: write bf16 split of result into g_Ah/g_Al (node rows) + logit partials g_lp.
// layer==2: write fp32 h to hout and bf16 split into g_Ah/g_Al rows 0..1023 (FC input).
#define BM 64
#define BN 64
#define BK 16
__global__ void k_agg(const float* __restrict__ HW, const float* __restrict__ bias,
                      float* __restrict__ hout, int layer) {
    __shared__ float As[BK][BM];
    __shared__ float Bs[BK][BN];
    int tid = threadIdx.x;
    int tx = tid & 15, ty = tid >> 4;
    int la = tid * 4;
    int ar = la >> 4, ac = la & 15;
    int br = la >> 6, bc = la & 63;
    float acc[4][4] = {};

    if (blockIdx.x < 128) {
        int m0 = (blockIdx.x >> 3) * BM, n0 = (blockIdx.x & 7) * BN;
        #pragma unroll
        for (int k0 = 0; k0 < KPAD; k0 += BK) {
            float4 av = *reinterpret_cast<const float4*>(g_alphaS + (size_t)(m0 + ar) * KPAD + k0 + ac);
            As[ac + 0][ar] = av.x; As[ac + 1][ar] = av.y;
            As[ac + 2][ar] = av.z; As[ac + 3][ar] = av.w;
            float4 bv = *reinterpret_cast<const float4*>(HW + (size_t)(k0 + br) * D + n0 + bc);
            *reinterpret_cast<float4*>(&Bs[br][bc]) = bv;
            __syncthreads();
            #pragma unroll
            for (int kk = 0; kk < BK; kk++) {
                float a0 = As[kk][ty * 4 + 0], a1 = As[kk][ty * 4 + 1];
                float a2 = As[kk][ty * 4 + 2], a3 = As[kk][ty * 4 + 3];
                float b0 = Bs[kk][tx * 4 + 0], b1 = Bs[kk][tx * 4 + 1];
                float b2 = Bs[kk][tx * 4 + 2], b3 = Bs[kk][tx * 4 + 3];
                acc[0][0] += a0 * b0; acc[0][1] += a0 * b1; acc[0][2] += a0 * b2; acc[0][3] += a0 * b3;
                acc[1][0] += a1 * b0; acc[1][1] += a1 * b1; acc[1][2] += a1 * b2; acc[1][3] += a1 * b3;
                acc[2][0] += a2 * b0; acc[2][1] += a2 * b1; acc[2][2] += a2 * b2; acc[2][3] += a2 * b3;
                acc[3][0] += a3 * b0; acc[3][1] += a3 * b1; acc[3][2] += a3 * b2; acc[3][3] += a3 * b3;
            }
            __syncthreads();
        }
        int ntile = n0 >> 6;
        #pragma unroll
        for (int i = 0; i < 4; i++) {
            int r = m0 + ty * 4 + i;
            float aself = g_aselfS[r];
            int cb = n0 + tx * 4;
            float vv[4];
            #pragma unroll
            for (int j = 0; j < 4; j++) {
                float v = acc[i][j] + aself * HW[(size_t)(NP + r) * D + cb + j] + bias[cb + j];
                vv[j] = v > 0.f ? v : 0.f;
            }
            // bf16 split store
            int arow = (layer == 1) ? (NP + r) : r;
            int abase = arow * D + cb;
            __nv_bfloat16 h0 = __float2bfloat16(vv[0]), h1 = __float2bfloat16(vv[1]);
            __nv_bfloat16 h2 = __float2bfloat16(vv[2]), h3 = __float2bfloat16(vv[3]);
            *reinterpret_cast<__nv_bfloat162*>(g_Ah + abase)     = __nv_bfloat162(h0, h1);
            *reinterpret_cast<__nv_bfloat162*>(g_Ah + abase + 2) = __nv_bfloat162(h2, h3);
            *reinterpret_cast<__nv_bfloat162*>(g_Al + abase) =
                __nv_bfloat162(__float2bfloat16(vv[0] - __bfloat162float(h0)),
                               __float2bfloat16(vv[1] - __bfloat162float(h1)));
            *reinterpret_cast<__nv_bfloat162*>(g_Al + abase + 2) =
                __nv_bfloat162(__float2bfloat16(vv[2] - __bfloat162float(h2)),
                               __float2bfloat16(vv[3] - __bfloat162float(h3)));
            if (layer == 2) {
                *reinterpret_cast<float4*>(hout + (size_t)r * D + cb) =
                    make_float4(vv[0], vv[1], vv[2], vv[3]);
            } else {
                // logit partials for layer 2
                float s = vv[0] * g_v[2][cb] + vv[1] * g_v[2][cb + 1]
                        + vv[2] * g_v[2][cb + 2] + vv[3] * g_v[2][cb + 3];
                float t = vv[0] * g_v[3][cb] + vv[1] * g_v[3][cb + 1]
                        + vv[2] * g_v[3][cb + 2] + vv[3] * g_v[3][cb + 3];
                #pragma unroll
                for (int o = 1; o < 16; o <<= 1) {
                    s += __shfl_xor_sync(0xffffffffu, s, o);
                    t += __shfl_xor_sync(0xffffffffu, t, o);
                }
                if (tx == 0) { g_lp[ntile][NP + r][0] = s; g_lp[ntile][NP + r][1] = t; }
            }
        }
    } else {
        int b = blockIdx.x - 128;            // (8 ntiles, 2 mtiles, 8 splits)
        int n0 = (b & 7) * BN;
        int m0 = ((b >> 3) & 1) * BM;
        int z = b >> 4;
        int kbase = z * (NS / SPLITK);
        #pragma unroll
        for (int kk0 = 0; kk0 < NS / SPLITK; kk0 += BK) {
            int k0 = kbase + kk0;
            float4 av = make_float4(0.f, 0.f, 0.f, 0.f);
            if (m0 + ar < NP)
                av = *reinterpret_cast<const float4*>(g_alphaP + (size_t)(m0 + ar) * NS + k0 + ac);
            As[ac + 0][ar] = av.x; As[ac + 1][ar] = av.y;
            As[ac + 2][ar] = av.z; As[ac + 3][ar] = av.w;
            float4 bv = *reinterpret_cast<const float4*>(HW + (size_t)(NP + k0 + br) * D + n0 + bc);
            *reinterpret_cast<float4*>(&Bs[br][bc]) = bv;
            __syncthreads();
            #pragma unroll
            for (int kk = 0; kk < BK; kk++) {
                float a0 = As[kk][ty * 4 + 0], a1 = As[kk][ty * 4 + 1];
                float a2 = As[kk][ty * 4 + 2], a3 = As[kk][ty * 4 + 3];
                float b0 = Bs[kk][tx * 4 + 0], b1 = Bs[kk][tx * 4 + 1];
                float b2 = Bs[kk][tx * 4 + 2], b3 = Bs[kk][tx * 4 + 3];
                acc[0][0] += a0 * b0; acc[0][1] += a0 * b1; acc[0][2] += a0 * b2; acc[0][3] += a0 * b3;
                acc[1][0] += a1 * b0; acc[1][1] += a1 * b1; acc[1][2] += a1 * b2; acc[1][3] += a1 * b3;
                acc[2][0] += a2 * b0; acc[2][1] += a2 * b1; acc[2][2] += a2 * b2; acc[2][3] += a2 * b3;
                acc[3][0] += a3 * b0; acc[3][1] += a3 * b1; acc[3][2] += a3 * b2; acc[3][3] += a3 * b3;
            }
            __syncthreads();
        }
        float* part = g_ppart + (size_t)z * NP * D;
        #pragma unroll
        for (int i = 0; i < 4; i++) {
            int r = m0 + ty * 4 + i;
            if (r >= NP) continue;
            #pragma unroll
            for (int j = 0; j < 4; j++)
                part[(size_t)r * D + n0 + tx * 4 + j] = acc[i][j];
        }
    }
}

// finalize layer-1 proxies: sum parts + self + bias, relu -> bf16 split + logit partials
__global__ void k_prox_fin(const float* __restrict__ HW, const float* __restrict__ bias) {
    __shared__ float sh[8][2];
    int idx = blockIdx.x * blockDim.x + threadIdx.x;
    int tid = threadIdx.x;
    int p = idx / D, c = idx - p * D;
    float v = 0.f;
    #pragma unroll
    for (int z = 0; z < SPLITK; z++) v += g_ppart[(size_t)z * NP * D + idx];
    v += g_aselfP[p] * HW[(size_t)p * D + c] + bias[c];
    v = v > 0.f ? v : 0.f;
    __nv_bfloat16 hi = __float2bfloat16(v);
    g_Ah[p * D + c] = hi;
    g_Al[p * D + c] = __float2bfloat16(v - __bfloat162float(hi));

    // logit partials: block covers half a row (256 cols, same p)
    float s = v * g_v[2][c];
    float t = v * g_v[3][c];
    #pragma unroll
    for (int o = 16; o > 0; o >>= 1) {
        s += __shfl_xor_sync(0xffffffffu, s, o);
        t += __shfl_xor_sync(0xffffffffu, t, o);
    }
    if ((tid & 31) == 0) { sh[tid >> 5][0] = s; sh[tid >> 5][1] = t; }
    __syncthreads();
    if (tid == 0) {
        float ss = 0.f, tt = 0.f;
        #pragma unroll
        for (int i = 0; i < 8; i++) { ss += sh[i][0]; tt += sh[i][1]; }
        int half = (c >> 8) & 1;   // which half-row this block covered
        g_lp[half][p][0] = ss;
        g_lp[half][p][1] = tt;
    }
}

// layer-2 alpha: samples only; logits from g_lp partials (proxies: 2 tiles, samples: 8 tiles)
__global__ void k_alpha2() {
    int warp = blockIdx.x * 8 + (threadIdx.x >> 5);
    int lane = threadIdx.x & 31;
    int node = NP + warp;
    float lsn = 0.f, ldn = 0.f;
    #pragma unroll
    for (int ti = 0; ti < 8; ti++) {
        lsn += g_lp[ti][node][0];
        ldn += g_lp[ti][node][1];
    }
    float w[4], sum = 0.f;
    #pragma unroll
    for (int i = 0; i < 4; i++) {
        int p = lane + 32 * i;
        if (p < NP) {
            float lsp = g_lp[0][p][0] + g_lp[1][p][0];
            w[i] = __expf(lrelu(lsp + ldn));
        } else w[i] = 0.f;
        sum += w[i];
    }
    float wself = __expf(lrelu(lsn + ldn));
    #pragma unroll
    for (int o = 16; o > 0; o >>= 1) sum += __shfl_xor_sync(0xffffffffu, sum, o);
    float inv = 1.f / (sum + wself);
    #pragma unroll
    for (int i = 0; i < 4; i++) {
        int p = lane + 32 * i;
        if (p < KPAD) g_alphaS[(size_t)warp * KPAD + p] = w[i] * inv;
    }
    if (lane == 0) g_aselfS[warp] = wself * inv;
}

// ============================ launch ============================
extern "C" void kernel_launch(void* const* d_in, const int* in_sizes, int n_in,
                              void* d_out, int out_size) {
    const float* x    = (const float*)d_in[0];
    const float* prox = (const float*)d_in[1];
    const float* W1   = (const float*)d_in[2];
    const float* as1  = (const float*)d_in[3];
    const float* ad1  = (const float*)d_in[4];
    const float* b1   = (const float*)d_in[5];
    const float* W2   = (const float*)d_in[6];
    const float* as2  = (const float*)d_in[7];
    const float* ad2  = (const float*)d_in[8];
    const float* b2   = (const float*)d_in[9];
    const float* fcw  = (const float*)d_in[10];
    const float* fcb  = (const float*)d_in[11];
    float* out = (float*)d_out;

    float *pHW, *pLS, *pLD;
    __nv_bfloat16 *pAh, *pAl, *pW1h, *pW1l, *pW2h, *pW2l, *pFCh, *pFCl;
    cudaGetSymbolAddress((void**)&pHW, g_HW);
    cudaGetSymbolAddress((void**)&pLS, g_lsrc);
    cudaGetSymbolAddress((void**)&pLD, g_ldst);
    cudaGetSymbolAddress((void**)&pAh,  g_Ah);
    cudaGetSymbolAddress((void**)&pAl,  g_Al);
    cudaGetSymbolAddress((void**)&pW1h, g_W1h);
    cudaGetSymbolAddress((void**)&pW1l, g_W1l);
    cudaGetSymbolAddress((void**)&pW2h, g_W2h);
    cudaGetSymbolAddress((void**)&pW2l, g_W2l);
    cudaGetSymbolAddress((void**)&pFCh, g_FCh);
    cudaGetSymbolAddress((void**)&pFCl, g_FCl);

    cudaFuncSetAttribute(k_mma, cudaFuncAttributeMaxDynamicSharedMemorySize, 2 * STAGE_BYTES);

    dim3 mma_grid(D / 64, MPAD / 64);   // (8, 18)

    k_prep<<<dim3(16, 16, 4), 256>>>(W1, W2, fcw, as1, ad1, as2, ad2);

    // ---- layer 1
    k_cvt_log<<<MPAD, 128>>>(x, prox);
    k_mma<<<mma_grid, 256, 2 * STAGE_BYTES>>>(pAh, pAl, pW1h, pW1l, pHW, D, NN, D, nullptr);
    k_alpha<<<228, 256>>>(pLS, pLD, 1);
    k_agg<<<256, 256>>>(pHW, b1, nullptr, 1);
    k_prox_fin<<<NP * D / 256, 256>>>(pHW, b1);

    // ---- layer 2 (proxy aggregation unused downstream)
    k_mma<<<mma_grid, 256, 2 * STAGE_BYTES>>>(pAh, pAl, pW2h, pW2l, pHW, D, NN, D, nullptr);
    k_alpha2<<<128, 256>>>();
    k_agg<<<128, 256>>>(pHW, b2, out + NS * 100, 2);

    // ---- preds = h @ fc_w + fc_b (h bf16 split already in g_Ah/g_Al rows 0..1023)
    dim3 fc_grid(2, NS / 64);   // (2, 16)
    k_mma<<<fc_grid, 256, 2 * STAGE_BYTES>>>(pAh, pAl, pFCh, pFCl, out, 100, NS, 100, fcb);
}